// round 4
// baseline (speedup 1.0000x reference)
#include <cuda_runtime.h>
#include <cuda_bf16.h>
#include <cuda_fp16.h>
#include <math.h>

#define NPTS 262144
#define NP 10
#define NL 16
#define TSZ (1u << 19)
#define PTS_PER_BLOCK 40
#define THREADS 320

// byte offsets in dynamic smem (all 16B aligned)
#define OFF_WIH   0          // 32*96 bf162      = 12288 B
#define OFF_WHH   12288      // 64*96 ull(f32x2) = 49152 B
#define OFF_H2    61440      // 40*64 ull {h,h}  = 20480 B
#define OFF_EMB   81920      // 40*320 half      = 25600 B
#define OFF_WFC   107520     // 64 f32           = 256 B
#define OFF_GS    107776     // 16 f32           = 64 B
#define OFF_ANC   107840     // 40*10 f32        = 1600 B
#define SMEM_BYTES 109440

#define SCALE 8192.0f
#define INV_SCALE (1.0f / 8192.0f)

struct ResParams { float gs[NL]; };

typedef unsigned long long ull;

__device__ __forceinline__ float sigm(float x) { return 1.0f / (1.0f + __expf(-x)); }
__device__ __forceinline__ float tanh_fast(float x) {
    float r; asm("tanh.approx.f32 %0, %1;" : "=f"(r) : "f"(x)); return r;
}
__device__ __forceinline__ void fma2(ull& a, ull b, ull c) {
    asm("fma.rn.f32x2 %0, %1, %2, %0;" : "+l"(a) : "l"(b), "l"(c));
}
__device__ __forceinline__ ull splat2(float x) {
    ull r; asm("mov.b64 %0, {%1, %1};" : "=l"(r) : "f"(x)); return r;
}
__device__ __forceinline__ ull bf2_to_f32x2(unsigned v) {
    unsigned lo = v << 16, hi = v & 0xffff0000u;
    ull r; asm("mov.b64 %0, {%1, %2};" : "=l"(r) : "r"(lo), "r"(hi)); return r;
}
__device__ __forceinline__ float2 unp(ull a) {
    float2 f; asm("mov.b64 {%0, %1}, %2;" : "=f"(f.x), "=f"(f.y) : "l"(a)); return f;
}

__global__ __launch_bounds__(THREADS, 2)
void xyz_tpc_kernel(const float* __restrict__ xyzt,
                    const float2* __restrict__ tab,
                    const float* __restrict__ w_ih,
                    const float* __restrict__ w_hh,
                    const float* __restrict__ w_fc,
                    float* __restrict__ out,
                    ResParams rp)
{
    extern __shared__ char smc[];
    unsigned* wih2  = reinterpret_cast<unsigned*>(smc + OFF_WIH);   // bf162 pairs (rows ln, ln+32)
    ull*      whh2  = reinterpret_cast<ull*>(smc + OFF_WHH);        // f32x2 pairs
    ull*      h2    = reinterpret_cast<ull*>(smc + OFF_H2);         // {h,h} pairs
    __half*   embh  = reinterpret_cast<__half*>(smc + OFF_EMB);     // emb * 8192
    float*    wfc_sh= reinterpret_cast<float*>(smc + OFF_WFC);
    float*    gs_sh = reinterpret_cast<float*>(smc + OFF_GS);
    float*    anc_sh= reinterpret_cast<float*>(smc + OFF_ANC);

    const int tid = threadIdx.x;

    // ---- stage weights ----
    for (int i = tid; i < 32 * 96; i += THREADS) {
        int d = i / 96, r = i % 96, j = r >> 5, ln = r & 31;
        float a = w_ih[(ln + 64 * j) * 32 + d] * INV_SCALE;   // fold emb descale
        float b = w_ih[(ln + 64 * j + 32) * 32 + d] * INV_SCALE;
        __nv_bfloat162 p = __floats2bfloat162_rn(a, b);
        wih2[i] = *reinterpret_cast<unsigned*>(&p);
    }
    for (int i = tid; i < 64 * 96; i += THREADS) {
        int k = i / 96, r = i % 96, j = r >> 5, ln = r & 31;
        float2 p = make_float2(w_hh[(ln + 64 * j) * 64 + k],
                               w_hh[(ln + 64 * j + 32) * 64 + k]);
        whh2[i] = *reinterpret_cast<ull*>(&p);
    }
    if (tid < 64) wfc_sh[tid] = w_fc[tid];
    if (tid < 16) gs_sh[tid] = rp.gs[tid];
    __syncthreads();

    const int lane  = tid & 31;
    const int wrp   = tid >> 5;
    const int pbase = wrp * 4;
    const int gpt   = blockIdx.x * PTS_PER_BLOCK + pbase;
    if (gpt >= NPTS) return;   // warp-uniform

    float4 pt[4];
    #pragma unroll
    for (int q = 0; q < 4; ++q)
        pt[q] = reinterpret_cast<const float4*>(xyzt)[gpt + q];

    // ---------------- Phase 1: gather, shuffle-free ----------------
    // lane -> level l = lane>>1, piece group pg = lane&1 (pieces [5pg, 5pg+5))
    {
        const int l  = lane >> 1;
        const int pg = lane & 1;
        const float gsv = gs_sh[l];
        const float2* tl = tab + (size_t)l * TSZ;

        #pragma unroll
        for (int q = 0; q < 4; ++q) {
            float x = fminf(fmaxf(pt[q].x, -1.0f), 1.0f);
            float y = fminf(fmaxf(pt[q].y, -1.0f), 1.0f);
            float z = fminf(fmaxf(pt[q].z, -1.0f), 1.0f);
            float tx = __fdiv_rn(x + 1.0f, gsv);
            float ty = __fdiv_rn(y + 1.0f, gsv);
            float tz = __fdiv_rn(z + 1.0f, gsv);
            float bx = floorf(tx), by = floorf(ty), bz = floorf(tz);
            float wx = __fdiv_rn(x - (bx * gsv - 1.0f), gsv);
            float wy = __fdiv_rn(y - (by * gsv - 1.0f), gsv);
            float wz = __fdiv_rn(z - (bz * gsv - 1.0f), gsv);

            unsigned ix = (unsigned)(int)bx;
            unsigned iy = (unsigned)(int)by;
            unsigned iz = (unsigned)(int)bz;
            unsigned hy0 = iy * 2654435761u, hy1 = hy0 + 2654435761u;
            unsigned hz0 = iz * 805459861u,  hz1 = hz0 + 805459861u;

            unsigned hidx[8];
            float    wc[8];
            float wx1 = 1.0f - wx, wy1 = 1.0f - wy, wz1 = 1.0f - wz;
            #pragma unroll
            for (int c = 0; c < 8; ++c) {
                unsigned hx = ix + ((c >> 2) & 1);
                unsigned hy = (c & 2) ? hy1 : hy0;
                unsigned hz = (c & 1) ? hz1 : hz0;
                hidx[c] = (hx ^ hy ^ hz) & (TSZ - 1u);
                wc[c] = (((c >> 2) & 1) ? wx : wx1) * ((c & 2) ? wy : wy1) * ((c & 1) ? wz : wz1);
            }

            __half2* ebase = reinterpret_cast<__half2*>(embh) + (pbase + q) * 160 + l;
            #pragma unroll
            for (int pp = 0; pp < 5; ++pp) {
                int p = pg * 5 + pp;
                const float2* sp = tl + (size_t)p * (size_t)(NL * (size_t)TSZ);
                float2 v[8];
                #pragma unroll
                for (int c = 0; c < 8; ++c) v[c] = __ldg(sp + hidx[c]);
                float ex = 0.0f, ey = 0.0f;
                #pragma unroll
                for (int c = 0; c < 8; ++c) { ex = fmaf(wc[c], v[c].x, ex); ey = fmaf(wc[c], v[c].y, ey); }
                ebase[p * 16] = __floats2half2_rn(ex * SCALE, ey * SCALE);
            }
        }
    }
    __syncwarp();

    // ---------------- Phase 2: GRU ----------------
    float h0[4] = {0,0,0,0}, h1[4] = {0,0,0,0};
    float anc[4] = {0,0,0,0};
    ull* h2w = h2 + wrp * 256;   // [q][k] pairs

    for (int p = 0; p < NP; ++p) {
        ull ar[4], az[4], ai[4], anh[4];
        #pragma unroll
        for (int q = 0; q < 4; ++q) { ar[q] = 0ull; az[q] = 0ull; ai[q] = 0ull; anh[q] = 0ull; }

        // gi = w_ih @ emb_p   (emb fp16 scaled; wih bf162 carries 1/8192)
        #pragma unroll
        for (int d8 = 0; d8 < 32; d8 += 8) {
            float2 ef[4][4];
            #pragma unroll
            for (int q = 0; q < 4; ++q) {
                uint4 raw = *reinterpret_cast<const uint4*>(
                    embh + (pbase + q) * 320 + p * 32 + d8);
                ef[q][0] = __half22float2(*reinterpret_cast<__half2*>(&raw.x));
                ef[q][1] = __half22float2(*reinterpret_cast<__half2*>(&raw.y));
                ef[q][2] = __half22float2(*reinterpret_cast<__half2*>(&raw.z));
                ef[q][3] = __half22float2(*reinterpret_cast<__half2*>(&raw.w));
            }
            #pragma unroll
            for (int j = 0; j < 4; ++j) {
                #pragma unroll
                for (int hi = 0; hi < 2; ++hi) {
                    int d = d8 + 2 * j + hi;
                    ull w0 = bf2_to_f32x2(wih2[d * 96 + lane]);
                    ull w1 = bf2_to_f32x2(wih2[d * 96 + 32 + lane]);
                    ull w2 = bf2_to_f32x2(wih2[d * 96 + 64 + lane]);
                    #pragma unroll
                    for (int q = 0; q < 4; ++q) {
                        ull ee = splat2(hi ? ef[q][j].y : ef[q][j].x);
                        fma2(ar[q], w0, ee);
                        fma2(az[q], w1, ee);
                        fma2(ai[q], w2, ee);
                    }
                }
            }
        }

        // gh = w_hh @ h_prev (from {h,h}-pair smem; weights pre-split f32x2)
        if (p > 0) {
            #pragma unroll 8
            for (int k2 = 0; k2 < 64; k2 += 2) {
                ulonglong2 hh[4];
                #pragma unroll
                for (int q = 0; q < 4; ++q)
                    hh[q] = *reinterpret_cast<const ulonglong2*>(h2w + q * 64 + k2);
                #pragma unroll
                for (int kk = 0; kk < 2; ++kk) {
                    int k = k2 + kk;
                    ull w0 = whh2[k * 96 + lane];
                    ull w1 = whh2[k * 96 + 32 + lane];
                    ull w2 = whh2[k * 96 + 64 + lane];
                    #pragma unroll
                    for (int q = 0; q < 4; ++q) {
                        ull hk = kk ? hh[q].y : hh[q].x;
                        fma2(ar[q], w0, hk);
                        fma2(az[q], w1, hk);
                        fma2(anh[q], w2, hk);
                    }
                }
            }
        }

        __syncwarp();
        // gates + h update + anchor
        #pragma unroll
        for (int q = 0; q < 4; ++q) {
            float2 fr = unp(ar[q]), fz = unp(az[q]), fi = unp(ai[q]), fn = unp(anh[q]);
            float r0 = sigm(fr.x), r1 = sigm(fr.y);
            float z0 = sigm(fz.x), z1 = sigm(fz.y);
            float n0 = tanh_fast(fi.x + r0 * fn.x);
            float n1 = tanh_fast(fi.y + r1 * fn.y);
            h0[q] = (1.0f - z0) * n0 + z0 * h0[q];
            h1[q] = (1.0f - z1) * n1 + z1 * h1[q];

            h2w[q * 64 + lane]      = splat2(h0[q]);
            h2w[q * 64 + 32 + lane] = splat2(h1[q]);

            float part = h0[q] * wfc_sh[lane] + h1[q] * wfc_sh[lane + 32];
            #pragma unroll
            for (int m = 16; m >= 1; m >>= 1)
                part += __shfl_xor_sync(0xffffffffu, part, m);
            anc[q] += __fdiv_rn(part * 2.0f, 10.0f);
            if (lane == 0) anc_sh[(pbase + q) * NP + p] = anc[q];
        }
        __syncwarp();
    }

    // ---------------- Phase 3: softmax + output ----------------
    #pragma unroll
    for (int q = 0; q < 4; ++q) {
        float t = pt[q].w;
        float lg[NP];
        float mx = -1e30f;
        #pragma unroll
        for (int p = 0; p < NP; ++p) {
            float a = anc_sh[(pbase + q) * NP + p];
            float L = -__fdiv_rn(fabsf(t - a), 100.0f);
            lg[p] = L;
            mx = fmaxf(mx, L);
        }
        float s = 0.0f, o = 0.0f;
        #pragma unroll
        for (int p = 0; p < NP; ++p) {
            float w = __expf(lg[p] - mx);
            s += w;
            float e = __half2float(embh[(pbase + q) * 320 + p * 32 + lane]);
            o += w * e;
        }
        out[(size_t)(gpt + q) * 32 + lane] = __fdiv_rn(o, s) * INV_SCALE;
    }
}

extern "C" void kernel_launch(void* const* d_in, const int* in_sizes, int n_in,
                              void* d_out, int out_size)
{
    const float*  xyzt = (const float*)d_in[0];
    const float2* tab  = (const float2*)d_in[1];
    const float*  w_ih = (const float*)d_in[2];
    const float*  w_hh = (const float*)d_in[3];
    const float*  w_fc = (const float*)d_in[4];
    float* out = (float*)d_out;

    ResParams rp;
    double B = exp((log(4096.0) - log(128.0)) / 15.0);
    for (int l = 0; l < NL; ++l) {
        double v = floor(128.0 * pow(B, (double)l));
        rp.gs[l] = 2.0f / (float)v;
    }

    cudaFuncSetAttribute(xyz_tpc_kernel, cudaFuncAttributeMaxDynamicSharedMemorySize, SMEM_BYTES);

    dim3 grid((NPTS + PTS_PER_BLOCK - 1) / PTS_PER_BLOCK);
    xyz_tpc_kernel<<<grid, THREADS, SMEM_BYTES>>>(xyzt, tab, w_ih, w_hh, w_fc, out, rp);
}

// round 5
// speedup vs baseline: 1.0738x; 1.0738x over previous
#include <cuda_runtime.h>
#include <cuda_fp16.h>
#include <math.h>

#define NPTS 262144
#define NP 10
#define NL 16
#define TSZ (1u << 19)
#define PTS_PER_BLOCK 40
#define THREADS 320

// byte offsets in dynamic smem
#define OFF_WIH 0        // 32*96 half2  = 12288
#define OFF_WHH 12288    // 64*96 half2  = 24576
#define OFF_EMB 36864    // 40*320 half  = 25600
#define OFF_H   62464    // 10 warps * 4 * 64 half2 = 10240
#define OFF_WFC 72704    // 64 f32
#define OFF_GS  72960    // 16 f32
#define OFF_ANC 73024    // 40*10 f32 = 1600
#define SMEM_BYTES 74624

#define SCALE 8192.0f
#define INV_SCALE (1.0f / 8192.0f)

struct ResParams { float gs[NL]; };

__device__ __forceinline__ float sigm(float x) { return 1.0f / (1.0f + __expf(-x)); }
__device__ __forceinline__ float tanh_fast(float x) {
    float r; asm("tanh.approx.f32 %0, %1;" : "=f"(r) : "f"(x)); return r;
}

__global__ __launch_bounds__(THREADS, 3)
void xyz_tpc_kernel(const float* __restrict__ xyzt,
                    const float2* __restrict__ tab,
                    const float* __restrict__ w_ih,
                    const float* __restrict__ w_hh,
                    const float* __restrict__ w_fc,
                    float* __restrict__ out,
                    ResParams rp)
{
    extern __shared__ char smc[];
    __half2* wih2   = reinterpret_cast<__half2*>(smc + OFF_WIH);
    __half2* whh2   = reinterpret_cast<__half2*>(smc + OFF_WHH);
    __half*  embh   = reinterpret_cast<__half*>(smc + OFF_EMB);
    __half2* h_sh   = reinterpret_cast<__half2*>(smc + OFF_H);
    float*   wfc_sh = reinterpret_cast<float*>(smc + OFF_WFC);
    float*   gs_sh  = reinterpret_cast<float*>(smc + OFF_GS);
    float*   anc_sh = reinterpret_cast<float*>(smc + OFF_ANC);

    const int tid = threadIdx.x;

    // ---- stage weights as half2 pairs: pair j covers rows (ln+64j, ln+64j+32) ----
    for (int i = tid; i < 32 * 96; i += THREADS) {
        int d = i / 96, r = i % 96, j = r >> 5, ln = r & 31;
        wih2[i] = __floats2half2_rn(w_ih[(ln + 64 * j) * 32 + d],
                                    w_ih[(ln + 64 * j + 32) * 32 + d]);
    }
    for (int i = tid; i < 64 * 96; i += THREADS) {
        int k = i / 96, r = i % 96, j = r >> 5, ln = r & 31;
        whh2[i] = __floats2half2_rn(w_hh[(ln + 64 * j) * 64 + k],
                                    w_hh[(ln + 64 * j + 32) * 64 + k]);
    }
    if (tid < 64) wfc_sh[tid] = w_fc[tid];
    if (tid < 16) gs_sh[tid] = rp.gs[tid];
    __syncthreads();

    const int lane  = tid & 31;
    const int wrp   = tid >> 5;
    const int pbase = wrp * 4;
    const int gpt   = blockIdx.x * PTS_PER_BLOCK + pbase;
    if (gpt >= NPTS) return;   // warp-uniform

    // ---------------- Phase 1: shuffle-free hash-grid gather ----------------
    // lane -> level l = lane>>1, piece group pg = lane&1 (pieces [5pg, 5pg+5))
    {
        const int l  = lane >> 1;
        const int pg = lane & 1;
        const float gsv = gs_sh[l];
        const float2* tl = tab + (size_t)l * TSZ;

        for (int q = 0; q < 4; ++q) {
            float4 ptq = reinterpret_cast<const float4*>(xyzt)[gpt + q];
            float x = fminf(fmaxf(ptq.x, -1.0f), 1.0f);
            float y = fminf(fmaxf(ptq.y, -1.0f), 1.0f);
            float z = fminf(fmaxf(ptq.z, -1.0f), 1.0f);
            float bx = floorf(__fdiv_rn(x + 1.0f, gsv));
            float by = floorf(__fdiv_rn(y + 1.0f, gsv));
            float bz = floorf(__fdiv_rn(z + 1.0f, gsv));
            float wx = __fdiv_rn(x - (bx * gsv - 1.0f), gsv);
            float wy = __fdiv_rn(y - (by * gsv - 1.0f), gsv);
            float wz = __fdiv_rn(z - (bz * gsv - 1.0f), gsv);

            unsigned ix = (unsigned)(int)bx;
            unsigned iy = (unsigned)(int)by;
            unsigned iz = (unsigned)(int)bz;
            unsigned hy0 = iy * 2654435761u, hy1 = hy0 + 2654435761u;
            unsigned hz0 = iz * 805459861u,  hz1 = hz0 + 805459861u;

            unsigned hidx[8];
            float    wc[8];
            float wx1 = 1.0f - wx, wy1 = 1.0f - wy, wz1 = 1.0f - wz;
            #pragma unroll
            for (int c = 0; c < 8; ++c) {
                unsigned hx = ix + ((c >> 2) & 1);
                unsigned hy = (c & 2) ? hy1 : hy0;
                unsigned hz = (c & 1) ? hz1 : hz0;
                hidx[c] = (hx ^ hy ^ hz) & (TSZ - 1u);
                wc[c] = (((c >> 2) & 1) ? wx : wx1) * ((c & 2) ? wy : wy1) * ((c & 1) ? wz : wz1);
            }

            __half2* ebase = reinterpret_cast<__half2*>(embh) + (pbase + q) * 160 + l;
            #pragma unroll
            for (int pp = 0; pp < 5; ++pp) {
                int p = pg * 5 + pp;
                const float2* sp = tl + (size_t)p * (size_t)(NL * (size_t)TSZ);
                float2 v[8];
                #pragma unroll
                for (int c = 0; c < 8; ++c) v[c] = __ldg(sp + hidx[c]);
                float ex = 0.0f, ey = 0.0f;
                #pragma unroll
                for (int c = 0; c < 8; ++c) { ex = fmaf(wc[c], v[c].x, ex); ey = fmaf(wc[c], v[c].y, ey); }
                ebase[p * 16] = __floats2half2_rn(ex * SCALE, ey * SCALE);
            }
        }
    }
    __syncwarp();

    // ---------------- Phase 2: GRU in half2 (HFMA2) ----------------
    float h0[4] = {0,0,0,0}, h1[4] = {0,0,0,0};
    float anc[4] = {0,0,0,0};
    __half2* hw = h_sh + wrp * 256;     // [q][64] pre-splatted {h,h}
    const __half2 z2 = __float2half2_rn(0.0f);

    for (int p = 0; p < NP; ++p) {
        __half2 gr[4], gz[4], gn[4];    // gi accums (scaled by 8192)
        __half2 hr[4], hz[4], hn[4];    // gh accums
        #pragma unroll
        for (int q = 0; q < 4; ++q) { gr[q]=z2; gz[q]=z2; gn[q]=z2; hr[q]=z2; hz[q]=z2; hn[q]=z2; }

        // gi = w_ih @ emb_p
        #pragma unroll
        for (int d8 = 0; d8 < 32; d8 += 8) {
            __half2 e[4][4];
            #pragma unroll
            for (int q = 0; q < 4; ++q) {
                uint4 raw = *reinterpret_cast<const uint4*>(embh + (pbase + q) * 320 + p * 32 + d8);
                e[q][0] = *reinterpret_cast<__half2*>(&raw.x);
                e[q][1] = *reinterpret_cast<__half2*>(&raw.y);
                e[q][2] = *reinterpret_cast<__half2*>(&raw.z);
                e[q][3] = *reinterpret_cast<__half2*>(&raw.w);
            }
            #pragma unroll
            for (int j = 0; j < 4; ++j) {
                #pragma unroll
                for (int hi = 0; hi < 2; ++hi) {
                    int d = d8 + 2 * j + hi;
                    __half2 w0 = wih2[d * 96 + lane];
                    __half2 w1 = wih2[d * 96 + 32 + lane];
                    __half2 w2 = wih2[d * 96 + 64 + lane];
                    #pragma unroll
                    for (int q = 0; q < 4; ++q) {
                        __half2 es = hi ? __high2half2(e[q][j]) : __low2half2(e[q][j]);
                        gr[q] = __hfma2(w0, es, gr[q]);
                        gz[q] = __hfma2(w1, es, gz[q]);
                        gn[q] = __hfma2(w2, es, gn[q]);
                    }
                }
            }
        }

        // gh = w_hh @ h_prev  (h pre-splatted in smem, LDS.128 broadcast)
        if (p > 0) {
            #pragma unroll 4
            for (int k4 = 0; k4 < 64; k4 += 4) {
                uint4 hq[4];
                #pragma unroll
                for (int q = 0; q < 4; ++q)
                    hq[q] = *reinterpret_cast<const uint4*>(hw + q * 64 + k4);
                #pragma unroll
                for (int kk = 0; kk < 4; ++kk) {
                    int k = k4 + kk;
                    __half2 w0 = whh2[k * 96 + lane];
                    __half2 w1 = whh2[k * 96 + 32 + lane];
                    __half2 w2 = whh2[k * 96 + 64 + lane];
                    #pragma unroll
                    for (int q = 0; q < 4; ++q) {
                        unsigned u = (kk == 0) ? hq[q].x : (kk == 1) ? hq[q].y
                                   : (kk == 2) ? hq[q].z : hq[q].w;
                        __half2 hs = *reinterpret_cast<__half2*>(&u);
                        hr[q] = __hfma2(w0, hs, hr[q]);
                        hz[q] = __hfma2(w1, hs, hz[q]);
                        hn[q] = __hfma2(w2, hs, hn[q]);
                    }
                }
            }
        }

        // gates + h update + anchor (fp32)
        #pragma unroll
        for (int q = 0; q < 4; ++q) {
            float2 fgr = __half22float2(gr[q]), fhr = __half22float2(hr[q]);
            float2 fgz = __half22float2(gz[q]), fhz = __half22float2(hz[q]);
            float2 fgn = __half22float2(gn[q]), fhn = __half22float2(hn[q]);
            float r0 = sigm(fgr.x * INV_SCALE + fhr.x);
            float r1 = sigm(fgr.y * INV_SCALE + fhr.y);
            float z0 = sigm(fgz.x * INV_SCALE + fhz.x);
            float z1 = sigm(fgz.y * INV_SCALE + fhz.y);
            float n0 = tanh_fast(fgn.x * INV_SCALE + r0 * fhn.x);
            float n1 = tanh_fast(fgn.y * INV_SCALE + r1 * fhn.y);
            h0[q] = (1.0f - z0) * n0 + z0 * h0[q];
            h1[q] = (1.0f - z1) * n1 + z1 * h1[q];

            hw[q * 64 + lane]      = __half2half2(__float2half_rn(h0[q]));
            hw[q * 64 + 32 + lane] = __half2half2(__float2half_rn(h1[q]));

            float part = h0[q] * wfc_sh[lane] + h1[q] * wfc_sh[lane + 32];
            #pragma unroll
            for (int m = 16; m >= 1; m >>= 1)
                part += __shfl_xor_sync(0xffffffffu, part, m);
            anc[q] += __fdiv_rn(part * 2.0f, 10.0f);
            if (lane == 0) anc_sh[(pbase + q) * NP + p] = anc[q];
        }
        __syncwarp();
    }

    // ---------------- Phase 3: softmax + output ----------------
    #pragma unroll
    for (int q = 0; q < 4; ++q) {
        float t = xyzt[(size_t)(gpt + q) * 4 + 3];
        float lg[NP];
        float mx = -1e30f;
        #pragma unroll
        for (int p = 0; p < NP; ++p) {
            float a = anc_sh[(pbase + q) * NP + p];
            float L = -__fdiv_rn(fabsf(t - a), 100.0f);
            lg[p] = L;
            mx = fmaxf(mx, L);
        }
        float s = 0.0f, o = 0.0f;
        #pragma unroll
        for (int p = 0; p < NP; ++p) {
            float w = __expf(lg[p] - mx);
            s += w;
            o += w * __half2float(embh[(pbase + q) * 320 + p * 32 + lane]);
        }
        out[(size_t)(gpt + q) * 32 + lane] = __fdiv_rn(o, s) * INV_SCALE;
    }
}

extern "C" void kernel_launch(void* const* d_in, const int* in_sizes, int n_in,
                              void* d_out, int out_size)
{
    const float*  xyzt = (const float*)d_in[0];
    const float2* tab  = (const float2*)d_in[1];
    const float*  w_ih = (const float*)d_in[2];
    const float*  w_hh = (const float*)d_in[3];
    const float*  w_fc = (const float*)d_in[4];
    float* out = (float*)d_out;

    ResParams rp;
    double B = exp((log(4096.0) - log(128.0)) / 15.0);
    for (int l = 0; l < NL; ++l) {
        double v = floor(128.0 * pow(B, (double)l));
        rp.gs[l] = 2.0f / (float)v;
    }

    cudaFuncSetAttribute(xyz_tpc_kernel, cudaFuncAttributeMaxDynamicSharedMemorySize, SMEM_BYTES);

    dim3 grid((NPTS + PTS_PER_BLOCK - 1) / PTS_PER_BLOCK);
    xyz_tpc_kernel<<<grid, THREADS, SMEM_BYTES>>>(xyzt, tab, w_ih, w_hh, w_fc, out, rp);
}

// round 6
// speedup vs baseline: 1.1094x; 1.0331x over previous
#include <cuda_runtime.h>
#include <cuda_fp16.h>
#include <math.h>

#define NPTS 262144
#define NP 10
#define NL 16
#define TSZ (1u << 19)
#define PTS_PER_BLOCK 32
#define THREADS 256

// byte offsets in dynamic smem
#define OFF_WIH 0        // 32*96 half2  = 12288
#define OFF_WHH 12288    // 64*96 half2  = 24576
#define OFF_EMB 36864    // 32*320 half  = 20480
#define OFF_H   57344    // 8 warps * 4 * 64 half2 = 8192
#define OFF_WFC 65536    // 64 f32
#define OFF_GS  65792    // 16 f32
#define OFF_ANC 65856    // 32*10 f32 = 1280
#define SMEM_BYTES 67136

#define SCALE 8192.0f
#define INV_SCALE (1.0f / 8192.0f)

struct ResParams { float gs[NL]; };

__device__ __forceinline__ float sigm(float x) { return 1.0f / (1.0f + __expf(-x)); }
__device__ __forceinline__ float tanh_fast(float x) {
    float r; asm("tanh.approx.f32 %0, %1;" : "=f"(r) : "f"(x)); return r;
}

__global__ __launch_bounds__(THREADS, 3)
void xyz_tpc_kernel(const float* __restrict__ xyzt,
                    const float2* __restrict__ tab,
                    const float* __restrict__ w_ih,
                    const float* __restrict__ w_hh,
                    const float* __restrict__ w_fc,
                    float* __restrict__ out,
                    ResParams rp)
{
    extern __shared__ char smc[];
    __half2* wih2   = reinterpret_cast<__half2*>(smc + OFF_WIH);
    __half2* whh2   = reinterpret_cast<__half2*>(smc + OFF_WHH);
    __half*  embh   = reinterpret_cast<__half*>(smc + OFF_EMB);
    __half2* h_sh   = reinterpret_cast<__half2*>(smc + OFF_H);
    float*   wfc_sh = reinterpret_cast<float*>(smc + OFF_WFC);
    float*   gs_sh  = reinterpret_cast<float*>(smc + OFF_GS);
    float*   anc_sh = reinterpret_cast<float*>(smc + OFF_ANC);

    const int tid = threadIdx.x;

    // ---- stage weights as half2 pairs: pair j covers rows (ln+64j, ln+64j+32) ----
    for (int i = tid; i < 32 * 96; i += THREADS) {
        int d = i / 96, r = i % 96, j = r >> 5, ln = r & 31;
        wih2[i] = __floats2half2_rn(w_ih[(ln + 64 * j) * 32 + d],
                                    w_ih[(ln + 64 * j + 32) * 32 + d]);
    }
    for (int i = tid; i < 64 * 96; i += THREADS) {
        int k = i / 96, r = i % 96, j = r >> 5, ln = r & 31;
        whh2[i] = __floats2half2_rn(w_hh[(ln + 64 * j) * 64 + k],
                                    w_hh[(ln + 64 * j + 32) * 64 + k]);
    }
    if (tid < 64) wfc_sh[tid] = w_fc[tid];
    if (tid < 16) gs_sh[tid] = rp.gs[tid];
    __syncthreads();

    const int lane  = tid & 31;
    const int wrp   = tid >> 5;
    const int pbase = wrp * 4;
    const int gpt   = blockIdx.x * PTS_PER_BLOCK + pbase;

    // ---------------- Phase 1: shuffle-free hash-grid gather ----------------
    // lane -> level l = lane>>1, piece group pg = lane&1 (pieces [5pg, 5pg+5))
    {
        const int l  = lane >> 1;
        const int pg = lane & 1;
        const float gsv = gs_sh[l];
        const float2* tl = tab + (size_t)l * TSZ;

        for (int q = 0; q < 4; ++q) {
            float4 ptq = reinterpret_cast<const float4*>(xyzt)[gpt + q];
            float x = fminf(fmaxf(ptq.x, -1.0f), 1.0f);
            float y = fminf(fmaxf(ptq.y, -1.0f), 1.0f);
            float z = fminf(fmaxf(ptq.z, -1.0f), 1.0f);
            float bx = floorf(__fdiv_rn(x + 1.0f, gsv));
            float by = floorf(__fdiv_rn(y + 1.0f, gsv));
            float bz = floorf(__fdiv_rn(z + 1.0f, gsv));
            float wx = __fdiv_rn(x - (bx * gsv - 1.0f), gsv);
            float wy = __fdiv_rn(y - (by * gsv - 1.0f), gsv);
            float wz = __fdiv_rn(z - (bz * gsv - 1.0f), gsv);

            unsigned ix = (unsigned)(int)bx;
            unsigned iy = (unsigned)(int)by;
            unsigned iz = (unsigned)(int)bz;
            unsigned hy0 = iy * 2654435761u, hy1 = hy0 + 2654435761u;
            unsigned hz0 = iz * 805459861u,  hz1 = hz0 + 805459861u;

            unsigned hidx[8];
            float    wc[8];
            float wx1 = 1.0f - wx, wy1 = 1.0f - wy, wz1 = 1.0f - wz;
            #pragma unroll
            for (int c = 0; c < 8; ++c) {
                unsigned hx = ix + ((c >> 2) & 1);
                unsigned hy = (c & 2) ? hy1 : hy0;
                unsigned hz = (c & 1) ? hz1 : hz0;
                hidx[c] = (hx ^ hy ^ hz) & (TSZ - 1u);
                wc[c] = (((c >> 2) & 1) ? wx : wx1) * ((c & 2) ? wy : wy1) * ((c & 1) ? wz : wz1);
            }

            __half2* ebase = reinterpret_cast<__half2*>(embh) + (pbase + q) * 160 + l;
            #pragma unroll
            for (int pp = 0; pp < 5; ++pp) {
                int p = pg * 5 + pp;
                const float2* sp = tl + (size_t)p * (size_t)(NL * (size_t)TSZ);
                float2 v[8];
                #pragma unroll
                for (int c = 0; c < 8; ++c) v[c] = __ldg(sp + hidx[c]);
                float ex = 0.0f, ey = 0.0f;
                #pragma unroll
                for (int c = 0; c < 8; ++c) { ex = fmaf(wc[c], v[c].x, ex); ey = fmaf(wc[c], v[c].y, ey); }
                ebase[p * 16] = __floats2half2_rn(ex * SCALE, ey * SCALE);
            }
        }
    }
    __syncwarp();

    // ---------------- Phase 2: GRU in half2 (HFMA2) ----------------
    float h0[4] = {0,0,0,0}, h1[4] = {0,0,0,0};
    float anc[4] = {0,0,0,0};
    __half2* hw = h_sh + wrp * 256;     // [q][64] pre-splatted {h,h}
    const __half2 z2 = __float2half2_rn(0.0f);

    for (int p = 0; p < NP; ++p) {
        __half2 gr[4], gz[4], gn[4];    // gi accums (scaled by 8192)
        __half2 hr[4], hz[4], hn[4];    // gh accums
        #pragma unroll
        for (int q = 0; q < 4; ++q) { gr[q]=z2; gz[q]=z2; gn[q]=z2; hr[q]=z2; hz[q]=z2; hn[q]=z2; }

        // gi = w_ih @ emb_p
        #pragma unroll
        for (int d8 = 0; d8 < 32; d8 += 8) {
            __half2 e[4][4];
            #pragma unroll
            for (int q = 0; q < 4; ++q) {
                uint4 raw = *reinterpret_cast<const uint4*>(embh + (pbase + q) * 320 + p * 32 + d8);
                e[q][0] = *reinterpret_cast<__half2*>(&raw.x);
                e[q][1] = *reinterpret_cast<__half2*>(&raw.y);
                e[q][2] = *reinterpret_cast<__half2*>(&raw.z);
                e[q][3] = *reinterpret_cast<__half2*>(&raw.w);
            }
            #pragma unroll
            for (int j = 0; j < 4; ++j) {
                #pragma unroll
                for (int hi = 0; hi < 2; ++hi) {
                    int d = d8 + 2 * j + hi;
                    __half2 w0 = wih2[d * 96 + lane];
                    __half2 w1 = wih2[d * 96 + 32 + lane];
                    __half2 w2 = wih2[d * 96 + 64 + lane];
                    #pragma unroll
                    for (int q = 0; q < 4; ++q) {
                        __half2 es = hi ? __high2half2(e[q][j]) : __low2half2(e[q][j]);
                        gr[q] = __hfma2(w0, es, gr[q]);
                        gz[q] = __hfma2(w1, es, gz[q]);
                        gn[q] = __hfma2(w2, es, gn[q]);
                    }
                }
            }
        }

        // gh = w_hh @ h_prev  (h pre-splatted in smem, LDS.128 broadcast)
        if (p > 0) {
            #pragma unroll 4
            for (int k4 = 0; k4 < 64; k4 += 4) {
                uint4 hq[4];
                #pragma unroll
                for (int q = 0; q < 4; ++q)
                    hq[q] = *reinterpret_cast<const uint4*>(hw + q * 64 + k4);
                #pragma unroll
                for (int kk = 0; kk < 4; ++kk) {
                    int k = k4 + kk;
                    __half2 w0 = whh2[k * 96 + lane];
                    __half2 w1 = whh2[k * 96 + 32 + lane];
                    __half2 w2 = whh2[k * 96 + 64 + lane];
                    #pragma unroll
                    for (int q = 0; q < 4; ++q) {
                        unsigned u = (kk == 0) ? hq[q].x : (kk == 1) ? hq[q].y
                                   : (kk == 2) ? hq[q].z : hq[q].w;
                        __half2 hs = *reinterpret_cast<__half2*>(&u);
                        hr[q] = __hfma2(w0, hs, hr[q]);
                        hz[q] = __hfma2(w1, hs, hz[q]);
                        hn[q] = __hfma2(w2, hs, hn[q]);
                    }
                }
            }
        }

        // gates + h update + anchor (fp32)
        #pragma unroll
        for (int q = 0; q < 4; ++q) {
            float2 fgr = __half22float2(gr[q]), fhr = __half22float2(hr[q]);
            float2 fgz = __half22float2(gz[q]), fhz = __half22float2(hz[q]);
            float2 fgn = __half22float2(gn[q]), fhn = __half22float2(hn[q]);
            float r0 = sigm(fgr.x * INV_SCALE + fhr.x);
            float r1 = sigm(fgr.y * INV_SCALE + fhr.y);
            float z0 = sigm(fgz.x * INV_SCALE + fhz.x);
            float z1 = sigm(fgz.y * INV_SCALE + fhz.y);
            float n0 = tanh_fast(fgn.x * INV_SCALE + r0 * fhn.x);
            float n1 = tanh_fast(fgn.y * INV_SCALE + r1 * fhn.y);
            h0[q] = (1.0f - z0) * n0 + z0 * h0[q];
            h1[q] = (1.0f - z1) * n1 + z1 * h1[q];

            hw[q * 64 + lane]      = __half2half2(__float2half_rn(h0[q]));
            hw[q * 64 + 32 + lane] = __half2half2(__float2half_rn(h1[q]));

            float part = h0[q] * wfc_sh[lane] + h1[q] * wfc_sh[lane + 32];
            #pragma unroll
            for (int m = 16; m >= 1; m >>= 1)
                part += __shfl_xor_sync(0xffffffffu, part, m);
            anc[q] += __fdiv_rn(part * 2.0f, 10.0f);
            if (lane == 0) anc_sh[(pbase + q) * NP + p] = anc[q];
        }
        __syncwarp();
    }

    // ---------------- Phase 3: softmax + output ----------------
    #pragma unroll
    for (int q = 0; q < 4; ++q) {
        float t = xyzt[(size_t)(gpt + q) * 4 + 3];
        float lg[NP];
        float mx = -1e30f;
        #pragma unroll
        for (int p = 0; p < NP; ++p) {
            float a = anc_sh[(pbase + q) * NP + p];
            float L = -__fdiv_rn(fabsf(t - a), 100.0f);
            lg[p] = L;
            mx = fmaxf(mx, L);
        }
        float s = 0.0f, o = 0.0f;
        #pragma unroll
        for (int p = 0; p < NP; ++p) {
            float w = __expf(lg[p] - mx);
            s += w;
            o += w * __half2float(embh[(pbase + q) * 320 + p * 32 + lane]);
        }
        out[(size_t)(gpt + q) * 32 + lane] = __fdiv_rn(o, s) * INV_SCALE;
    }
}

extern "C" void kernel_launch(void* const* d_in, const int* in_sizes, int n_in,
                              void* d_out, int out_size)
{
    const float*  xyzt = (const float*)d_in[0];
    const float2* tab  = (const float2*)d_in[1];
    const float*  w_ih = (const float*)d_in[2];
    const float*  w_hh = (const float*)d_in[3];
    const float*  w_fc = (const float*)d_in[4];
    float* out = (float*)d_out;

    ResParams rp;
    double B = exp((log(4096.0) - log(128.0)) / 15.0);
    for (int l = 0; l < NL; ++l) {
        double v = floor(128.0 * pow(B, (double)l));
        rp.gs[l] = 2.0f / (float)v;
    }

    cudaFuncSetAttribute(xyz_tpc_kernel, cudaFuncAttributeMaxDynamicSharedMemorySize, SMEM_BYTES);

    dim3 grid(NPTS / PTS_PER_BLOCK);
    xyz_tpc_kernel<<<grid, THREADS, SMEM_BYTES>>>(xyzt, tab, w_ih, w_hh, w_fc, out, rp);
}

// round 7
// speedup vs baseline: 2.6678x; 2.4048x over previous
#include <cuda_runtime.h>
#include <cuda_fp16.h>
#include <math.h>

#define NPTS 262144
#define NP 10
#define NL 16
#define TSZ (1u << 19)
#define PTS_PER_BLOCK 32
#define THREADS 256

#define SCALE 8192.0f
#define INV_SCALE (1.0f / 8192.0f)

// scratch: emb[point][piece][32 dims] as half (scaled by 8192). 262144*320*2B = 168MB
__device__ __half g_emb[(size_t)NPTS * 320];

struct ResParams { float gs[NL]; };

__device__ __forceinline__ float sigm(float x) { return 1.0f / (1.0f + __expf(-x)); }
__device__ __forceinline__ float tanh_fast(float x) {
    float r; asm("tanh.approx.f32 %0, %1;" : "=f"(r) : "f"(x)); return r;
}

// ===================== Kernel A: hash-grid gather =====================
// grid (NPTS/256, NL); blockIdx.y = level -> wave stays within ~1-2 levels,
// whose 10 piece-tables (40MB) are L2-resident. All lanes of a warp hit the
// same table per LDG (2 TLB pages / instruction).
__global__ __launch_bounds__(256)
void gather_kernel(const float* __restrict__ xyzt,
                   const float2* __restrict__ tab,
                   ResParams rp)
{
    const int l    = blockIdx.y;
    const int ptid = blockIdx.x * 256 + threadIdx.x;

    const float gsv = rp.gs[l];
    float4 ptq = reinterpret_cast<const float4*>(xyzt)[ptid];
    float x = fminf(fmaxf(ptq.x, -1.0f), 1.0f);
    float y = fminf(fmaxf(ptq.y, -1.0f), 1.0f);
    float z = fminf(fmaxf(ptq.z, -1.0f), 1.0f);
    float bx = floorf(__fdiv_rn(x + 1.0f, gsv));
    float by = floorf(__fdiv_rn(y + 1.0f, gsv));
    float bz = floorf(__fdiv_rn(z + 1.0f, gsv));
    float wx = __fdiv_rn(x - (bx * gsv - 1.0f), gsv);
    float wy = __fdiv_rn(y - (by * gsv - 1.0f), gsv);
    float wz = __fdiv_rn(z - (bz * gsv - 1.0f), gsv);

    unsigned ix = (unsigned)(int)bx;
    unsigned iy = (unsigned)(int)by;
    unsigned iz = (unsigned)(int)bz;
    unsigned hy0 = iy * 2654435761u, hy1 = hy0 + 2654435761u;
    unsigned hz0 = iz * 805459861u,  hz1 = hz0 + 805459861u;

    unsigned hidx[8];
    float    wc[8];
    float wx1 = 1.0f - wx, wy1 = 1.0f - wy, wz1 = 1.0f - wz;
    #pragma unroll
    for (int c = 0; c < 8; ++c) {
        unsigned hx = ix + ((c >> 2) & 1);
        unsigned hy = (c & 2) ? hy1 : hy0;
        unsigned hz = (c & 1) ? hz1 : hz0;
        hidx[c] = (hx ^ hy ^ hz) & (TSZ - 1u);
        wc[c] = (((c >> 2) & 1) ? wx : wx1) * ((c & 2) ? wy : wy1) * ((c & 1) ? wz : wz1);
    }

    const float2* tl = tab + (size_t)l * TSZ;
    __half2* eb = reinterpret_cast<__half2*>(g_emb) + (size_t)ptid * 160 + l;

    #pragma unroll 2
    for (int p = 0; p < NP; ++p) {
        const float2* sp = tl + (size_t)p * (size_t)(NL * (size_t)TSZ);
        float2 v[8];
        #pragma unroll
        for (int c = 0; c < 8; ++c) v[c] = __ldg(sp + hidx[c]);
        float ex = 0.0f, ey = 0.0f;
        #pragma unroll
        for (int c = 0; c < 8; ++c) { ex = fmaf(wc[c], v[c].x, ex); ey = fmaf(wc[c], v[c].y, ey); }
        eb[p * 16] = __floats2half2_rn(ex * SCALE, ey * SCALE);
    }
}

// ===================== Kernel B: GRU + softmax =====================
// byte offsets in dynamic smem
#define OFF_WIH 0        // 32*96 half2  = 12288
#define OFF_WHH 12288    // 64*96 half2  = 24576
#define OFF_EMB 36864    // 32*320 half  = 20480
#define OFF_H   57344    // 8 warps * 4 * 64 half2 = 8192
#define OFF_WFC 65536    // 64 f32
#define OFF_GS  65792    // pad
#define OFF_ANC 65856    // 32*10 f32 = 1280
#define SMEM_BYTES 67136

__global__ __launch_bounds__(THREADS, 3)
void gru_kernel(const float* __restrict__ xyzt,
                const float* __restrict__ w_ih,
                const float* __restrict__ w_hh,
                const float* __restrict__ w_fc,
                float* __restrict__ out)
{
    extern __shared__ char smc[];
    __half2* wih2   = reinterpret_cast<__half2*>(smc + OFF_WIH);
    __half2* whh2   = reinterpret_cast<__half2*>(smc + OFF_WHH);
    __half*  embh   = reinterpret_cast<__half*>(smc + OFF_EMB);
    __half2* h_sh   = reinterpret_cast<__half2*>(smc + OFF_H);
    float*   wfc_sh = reinterpret_cast<float*>(smc + OFF_WFC);
    float*   anc_sh = reinterpret_cast<float*>(smc + OFF_ANC);

    const int tid = threadIdx.x;

    // stage weights as half2 pairs: pair j covers rows (ln+64j, ln+64j+32)
    for (int i = tid; i < 32 * 96; i += THREADS) {
        int d = i / 96, r = i % 96, j = r >> 5, ln = r & 31;
        wih2[i] = __floats2half2_rn(w_ih[(ln + 64 * j) * 32 + d],
                                    w_ih[(ln + 64 * j + 32) * 32 + d]);
    }
    for (int i = tid; i < 64 * 96; i += THREADS) {
        int k = i / 96, r = i % 96, j = r >> 5, ln = r & 31;
        whh2[i] = __floats2half2_rn(w_hh[(ln + 64 * j) * 64 + k],
                                    w_hh[(ln + 64 * j + 32) * 64 + k]);
    }
    if (tid < 64) wfc_sh[tid] = w_fc[tid];

    // coalesced copy-in of this block's 32-point emb tile (20480 B)
    {
        const uint4* src = reinterpret_cast<const uint4*>(
            g_emb + (size_t)blockIdx.x * PTS_PER_BLOCK * 320);
        uint4* dst = reinterpret_cast<uint4*>(embh);
        #pragma unroll
        for (int i = 0; i < 5; ++i)
            dst[tid + i * THREADS] = src[tid + i * THREADS];
    }
    __syncthreads();

    const int lane  = tid & 31;
    const int wrp   = tid >> 5;
    const int pbase = wrp * 4;
    const int gpt   = blockIdx.x * PTS_PER_BLOCK + pbase;

    // ---------------- GRU in half2 (HFMA2) ----------------
    float h0[4] = {0,0,0,0}, h1[4] = {0,0,0,0};
    float anc[4] = {0,0,0,0};
    __half2* hw = h_sh + wrp * 256;     // [q][64] pre-splatted {h,h}
    const __half2 z2 = __float2half2_rn(0.0f);

    for (int p = 0; p < NP; ++p) {
        __half2 gr[4], gz[4], gn[4];
        __half2 hr[4], hz[4], hn[4];
        #pragma unroll
        for (int q = 0; q < 4; ++q) { gr[q]=z2; gz[q]=z2; gn[q]=z2; hr[q]=z2; hz[q]=z2; hn[q]=z2; }

        // gi = w_ih @ emb_p
        #pragma unroll
        for (int d8 = 0; d8 < 32; d8 += 8) {
            __half2 e[4][4];
            #pragma unroll
            for (int q = 0; q < 4; ++q) {
                uint4 raw = *reinterpret_cast<const uint4*>(embh + (pbase + q) * 320 + p * 32 + d8);
                e[q][0] = *reinterpret_cast<__half2*>(&raw.x);
                e[q][1] = *reinterpret_cast<__half2*>(&raw.y);
                e[q][2] = *reinterpret_cast<__half2*>(&raw.z);
                e[q][3] = *reinterpret_cast<__half2*>(&raw.w);
            }
            #pragma unroll
            for (int j = 0; j < 4; ++j) {
                #pragma unroll
                for (int hi = 0; hi < 2; ++hi) {
                    int d = d8 + 2 * j + hi;
                    __half2 w0 = wih2[d * 96 + lane];
                    __half2 w1 = wih2[d * 96 + 32 + lane];
                    __half2 w2 = wih2[d * 96 + 64 + lane];
                    #pragma unroll
                    for (int q = 0; q < 4; ++q) {
                        __half2 es = hi ? __high2half2(e[q][j]) : __low2half2(e[q][j]);
                        gr[q] = __hfma2(w0, es, gr[q]);
                        gz[q] = __hfma2(w1, es, gz[q]);
                        gn[q] = __hfma2(w2, es, gn[q]);
                    }
                }
            }
        }

        // gh = w_hh @ h_prev
        if (p > 0) {
            #pragma unroll 4
            for (int k4 = 0; k4 < 64; k4 += 4) {
                uint4 hq[4];
                #pragma unroll
                for (int q = 0; q < 4; ++q)
                    hq[q] = *reinterpret_cast<const uint4*>(hw + q * 64 + k4);
                #pragma unroll
                for (int kk = 0; kk < 4; ++kk) {
                    int k = k4 + kk;
                    __half2 w0 = whh2[k * 96 + lane];
                    __half2 w1 = whh2[k * 96 + 32 + lane];
                    __half2 w2 = whh2[k * 96 + 64 + lane];
                    #pragma unroll
                    for (int q = 0; q < 4; ++q) {
                        unsigned u = (kk == 0) ? hq[q].x : (kk == 1) ? hq[q].y
                                   : (kk == 2) ? hq[q].z : hq[q].w;
                        __half2 hs = *reinterpret_cast<__half2*>(&u);
                        hr[q] = __hfma2(w0, hs, hr[q]);
                        hz[q] = __hfma2(w1, hs, hz[q]);
                        hn[q] = __hfma2(w2, hs, hn[q]);
                    }
                }
            }
        }

        // gates + h update + anchor (fp32)
        #pragma unroll
        for (int q = 0; q < 4; ++q) {
            float2 fgr = __half22float2(gr[q]), fhr = __half22float2(hr[q]);
            float2 fgz = __half22float2(gz[q]), fhz = __half22float2(hz[q]);
            float2 fgn = __half22float2(gn[q]), fhn = __half22float2(hn[q]);
            float r0 = sigm(fgr.x * INV_SCALE + fhr.x);
            float r1 = sigm(fgr.y * INV_SCALE + fhr.y);
            float z0 = sigm(fgz.x * INV_SCALE + fhz.x);
            float z1 = sigm(fgz.y * INV_SCALE + fhz.y);
            float n0 = tanh_fast(fgn.x * INV_SCALE + r0 * fhn.x);
            float n1 = tanh_fast(fgn.y * INV_SCALE + r1 * fhn.y);
            h0[q] = (1.0f - z0) * n0 + z0 * h0[q];
            h1[q] = (1.0f - z1) * n1 + z1 * h1[q];

            hw[q * 64 + lane]      = __half2half2(__float2half_rn(h0[q]));
            hw[q * 64 + 32 + lane] = __half2half2(__float2half_rn(h1[q]));

            float part = h0[q] * wfc_sh[lane] + h1[q] * wfc_sh[lane + 32];
            #pragma unroll
            for (int m = 16; m >= 1; m >>= 1)
                part += __shfl_xor_sync(0xffffffffu, part, m);
            anc[q] += __fdiv_rn(part * 2.0f, 10.0f);
            if (lane == 0) anc_sh[(pbase + q) * NP + p] = anc[q];
        }
        __syncwarp();
    }

    // ---------------- softmax + output ----------------
    #pragma unroll
    for (int q = 0; q < 4; ++q) {
        float t = xyzt[(size_t)(gpt + q) * 4 + 3];
        float lg[NP];
        float mx = -1e30f;
        #pragma unroll
        for (int p = 0; p < NP; ++p) {
            float a = anc_sh[(pbase + q) * NP + p];
            float L = -__fdiv_rn(fabsf(t - a), 100.0f);
            lg[p] = L;
            mx = fmaxf(mx, L);
        }
        float s = 0.0f, o = 0.0f;
        #pragma unroll
        for (int p = 0; p < NP; ++p) {
            float w = __expf(lg[p] - mx);
            s += w;
            o += w * __half2float(embh[(pbase + q) * 320 + p * 32 + lane]);
        }
        out[(size_t)(gpt + q) * 32 + lane] = __fdiv_rn(o, s) * INV_SCALE;
    }
}

extern "C" void kernel_launch(void* const* d_in, const int* in_sizes, int n_in,
                              void* d_out, int out_size)
{
    const float*  xyzt = (const float*)d_in[0];
    const float2* tab  = (const float2*)d_in[1];
    const float*  w_ih = (const float*)d_in[2];
    const float*  w_hh = (const float*)d_in[3];
    const float*  w_fc = (const float*)d_in[4];
    float* out = (float*)d_out;

    ResParams rp;
    double B = exp((log(4096.0) - log(128.0)) / 15.0);
    for (int l = 0; l < NL; ++l) {
        double v = floor(128.0 * pow(B, (double)l));
        rp.gs[l] = 2.0f / (float)v;
    }

    cudaFuncSetAttribute(gru_kernel, cudaFuncAttributeMaxDynamicSharedMemorySize, SMEM_BYTES);

    dim3 gridA(NPTS / 256, NL);
    gather_kernel<<<gridA, 256>>>(xyzt, tab, rp);

    dim3 gridB(NPTS / PTS_PER_BLOCK);
    gru_kernel<<<gridB, THREADS, SMEM_BYTES>>>(xyzt, w_ih, w_hh, w_fc, out);
}

// round 8
// speedup vs baseline: 3.1699x; 1.1882x over previous
#include <cuda_runtime.h>
#include <cuda_fp16.h>
#include <math.h>

#define NPTS 262144
#define NP 10
#define NL 16
#define TSZ (1u << 19)
#define PTS_PER_BLOCK 32
#define THREADS 256

#define SCALE 8192.0f
#define INV_SCALE (1.0f / 8192.0f)

// scratch: emb[point][piece][32 dims] as half (scaled by 8192). 262144*320*2B = 168MB
__device__ __half g_emb[(size_t)NPTS * 320];
// transposed tables: [level][entry] -> 64B slot holding 10 half2 (pieces), pre-scaled by 8192
__device__ uint4 g_tabT[(size_t)NL * TSZ * 4];

struct ResParams { float gs[NL]; };

__device__ __forceinline__ float sigm(float x) { return 1.0f / (1.0f + __expf(-x)); }
__device__ __forceinline__ float tanh_fast(float x) {
    float r; asm("tanh.approx.f32 %0, %1;" : "=f"(r) : "f"(x)); return r;
}

// ===================== Kernel T: table transpose (piece-major -> entry-major) =====================
__global__ __launch_bounds__(256)
void transpose_kernel(const float2* __restrict__ tab)
{
    size_t idx = (size_t)blockIdx.x * 256 + threadIdx.x;   // = l*TSZ + e
    unsigned u[NP];
    #pragma unroll
    for (int p = 0; p < NP; ++p) {
        float2 v = __ldg(tab + (size_t)p * ((size_t)NL * TSZ) + idx);
        __half2 h = __floats2half2_rn(v.x * SCALE, v.y * SCALE);
        u[p] = *reinterpret_cast<unsigned*>(&h);
    }
    uint4* dst = g_tabT + idx * 4;
    dst[0] = make_uint4(u[0], u[1], u[2], u[3]);
    dst[1] = make_uint4(u[4], u[5], u[6], u[7]);
    *reinterpret_cast<uint2*>(dst + 2) = make_uint2(u[8], u[9]);
}

// ===================== Kernel A: hash-grid gather =====================
// grid (NPTS/256, NL); blockIdx.y = level -> per-level transposed table (32MB) is L2-resident.
// One corner = 3 LDG within one 64B slot = 1 cache line per lane.
__global__ __launch_bounds__(256)
void gather_kernel(const float* __restrict__ xyzt, ResParams rp)
{
    const int l    = blockIdx.y;
    const int ptid = blockIdx.x * 256 + threadIdx.x;

    const float gsv = rp.gs[l];
    float4 ptq = reinterpret_cast<const float4*>(xyzt)[ptid];
    float x = fminf(fmaxf(ptq.x, -1.0f), 1.0f);
    float y = fminf(fmaxf(ptq.y, -1.0f), 1.0f);
    float z = fminf(fmaxf(ptq.z, -1.0f), 1.0f);
    float bx = floorf(__fdiv_rn(x + 1.0f, gsv));
    float by = floorf(__fdiv_rn(y + 1.0f, gsv));
    float bz = floorf(__fdiv_rn(z + 1.0f, gsv));
    float wx = __fdiv_rn(x - (bx * gsv - 1.0f), gsv);
    float wy = __fdiv_rn(y - (by * gsv - 1.0f), gsv);
    float wz = __fdiv_rn(z - (bz * gsv - 1.0f), gsv);

    unsigned ix = (unsigned)(int)bx;
    unsigned iy = (unsigned)(int)by;
    unsigned iz = (unsigned)(int)bz;
    unsigned hy0 = iy * 2654435761u, hy1 = hy0 + 2654435761u;
    unsigned hz0 = iz * 805459861u,  hz1 = hz0 + 805459861u;

    unsigned hidx[8];
    float    wc[8];
    float wx1 = 1.0f - wx, wy1 = 1.0f - wy, wz1 = 1.0f - wz;
    #pragma unroll
    for (int c = 0; c < 8; ++c) {
        unsigned hx = ix + ((c >> 2) & 1);
        unsigned hy = (c & 2) ? hy1 : hy0;
        unsigned hz = (c & 1) ? hz1 : hz0;
        hidx[c] = (hx ^ hy ^ hz) & (TSZ - 1u);
        wc[c] = (((c >> 2) & 1) ? wx : wx1) * ((c & 2) ? wy : wy1) * ((c & 1) ? wz : wz1);
    }

    const uint4* lvl = g_tabT + (size_t)l * TSZ * 4;
    float sx[NP], sy[NP];
    #pragma unroll
    for (int p = 0; p < NP; ++p) { sx[p] = 0.0f; sy[p] = 0.0f; }

    #pragma unroll
    for (int c = 0; c < 8; ++c) {
        const uint4* s = lvl + (size_t)hidx[c] * 4;
        uint4 A = __ldg(s);
        uint4 B = __ldg(s + 1);
        uint2 C = __ldg(reinterpret_cast<const uint2*>(s + 2));
        unsigned u[NP] = {A.x, A.y, A.z, A.w, B.x, B.y, B.z, B.w, C.x, C.y};
        float w = wc[c];
        #pragma unroll
        for (int p = 0; p < NP; ++p) {
            float2 f = __half22float2(*reinterpret_cast<__half2*>(&u[p]));
            sx[p] = fmaf(w, f.x, sx[p]);
            sy[p] = fmaf(w, f.y, sy[p]);
        }
    }

    __half2* eb = reinterpret_cast<__half2*>(g_emb) + (size_t)ptid * 160 + l;
    #pragma unroll
    for (int p = 0; p < NP; ++p)
        eb[p * 16] = __floats2half2_rn(sx[p], sy[p]);   // already scaled by 8192
}

// ===================== Kernel B: GRU + softmax (unchanged from R7) =====================
#define OFF_WIH 0        // 32*96 half2  = 12288
#define OFF_WHH 12288    // 64*96 half2  = 24576
#define OFF_EMB 36864    // 32*320 half  = 20480
#define OFF_H   57344    // 8 warps * 4 * 64 half2 = 8192
#define OFF_WFC 65536    // 64 f32
#define OFF_ANC 65856    // 32*10 f32 = 1280
#define SMEM_BYTES 67136

__global__ __launch_bounds__(THREADS, 3)
void gru_kernel(const float* __restrict__ xyzt,
                const float* __restrict__ w_ih,
                const float* __restrict__ w_hh,
                const float* __restrict__ w_fc,
                float* __restrict__ out)
{
    extern __shared__ char smc[];
    __half2* wih2   = reinterpret_cast<__half2*>(smc + OFF_WIH);
    __half2* whh2   = reinterpret_cast<__half2*>(smc + OFF_WHH);
    __half*  embh   = reinterpret_cast<__half*>(smc + OFF_EMB);
    __half2* h_sh   = reinterpret_cast<__half2*>(smc + OFF_H);
    float*   wfc_sh = reinterpret_cast<float*>(smc + OFF_WFC);
    float*   anc_sh = reinterpret_cast<float*>(smc + OFF_ANC);

    const int tid = threadIdx.x;

    for (int i = tid; i < 32 * 96; i += THREADS) {
        int d = i / 96, r = i % 96, j = r >> 5, ln = r & 31;
        wih2[i] = __floats2half2_rn(w_ih[(ln + 64 * j) * 32 + d],
                                    w_ih[(ln + 64 * j + 32) * 32 + d]);
    }
    for (int i = tid; i < 64 * 96; i += THREADS) {
        int k = i / 96, r = i % 96, j = r >> 5, ln = r & 31;
        whh2[i] = __floats2half2_rn(w_hh[(ln + 64 * j) * 64 + k],
                                    w_hh[(ln + 64 * j + 32) * 64 + k]);
    }
    if (tid < 64) wfc_sh[tid] = w_fc[tid];

    {
        const uint4* src = reinterpret_cast<const uint4*>(
            g_emb + (size_t)blockIdx.x * PTS_PER_BLOCK * 320);
        uint4* dst = reinterpret_cast<uint4*>(embh);
        #pragma unroll
        for (int i = 0; i < 5; ++i)
            dst[tid + i * THREADS] = src[tid + i * THREADS];
    }
    __syncthreads();

    const int lane  = tid & 31;
    const int wrp   = tid >> 5;
    const int pbase = wrp * 4;
    const int gpt   = blockIdx.x * PTS_PER_BLOCK + pbase;

    float h0[4] = {0,0,0,0}, h1[4] = {0,0,0,0};
    float anc[4] = {0,0,0,0};
    __half2* hw = h_sh + wrp * 256;
    const __half2 z2 = __float2half2_rn(0.0f);

    for (int p = 0; p < NP; ++p) {
        __half2 gr[4], gz[4], gn[4];
        __half2 hr[4], hz[4], hn[4];
        #pragma unroll
        for (int q = 0; q < 4; ++q) { gr[q]=z2; gz[q]=z2; gn[q]=z2; hr[q]=z2; hz[q]=z2; hn[q]=z2; }

        #pragma unroll
        for (int d8 = 0; d8 < 32; d8 += 8) {
            __half2 e[4][4];
            #pragma unroll
            for (int q = 0; q < 4; ++q) {
                uint4 raw = *reinterpret_cast<const uint4*>(embh + (pbase + q) * 320 + p * 32 + d8);
                e[q][0] = *reinterpret_cast<__half2*>(&raw.x);
                e[q][1] = *reinterpret_cast<__half2*>(&raw.y);
                e[q][2] = *reinterpret_cast<__half2*>(&raw.z);
                e[q][3] = *reinterpret_cast<__half2*>(&raw.w);
            }
            #pragma unroll
            for (int j = 0; j < 4; ++j) {
                #pragma unroll
                for (int hi = 0; hi < 2; ++hi) {
                    int d = d8 + 2 * j + hi;
                    __half2 w0 = wih2[d * 96 + lane];
                    __half2 w1 = wih2[d * 96 + 32 + lane];
                    __half2 w2 = wih2[d * 96 + 64 + lane];
                    #pragma unroll
                    for (int q = 0; q < 4; ++q) {
                        __half2 es = hi ? __high2half2(e[q][j]) : __low2half2(e[q][j]);
                        gr[q] = __hfma2(w0, es, gr[q]);
                        gz[q] = __hfma2(w1, es, gz[q]);
                        gn[q] = __hfma2(w2, es, gn[q]);
                    }
                }
            }
        }

        if (p > 0) {
            #pragma unroll 4
            for (int k4 = 0; k4 < 64; k4 += 4) {
                uint4 hq[4];
                #pragma unroll
                for (int q = 0; q < 4; ++q)
                    hq[q] = *reinterpret_cast<const uint4*>(hw + q * 64 + k4);
                #pragma unroll
                for (int kk = 0; kk < 4; ++kk) {
                    int k = k4 + kk;
                    __half2 w0 = whh2[k * 96 + lane];
                    __half2 w1 = whh2[k * 96 + 32 + lane];
                    __half2 w2 = whh2[k * 96 + 64 + lane];
                    #pragma unroll
                    for (int q = 0; q < 4; ++q) {
                        unsigned u = (kk == 0) ? hq[q].x : (kk == 1) ? hq[q].y
                                   : (kk == 2) ? hq[q].z : hq[q].w;
                        __half2 hs = *reinterpret_cast<__half2*>(&u);
                        hr[q] = __hfma2(w0, hs, hr[q]);
                        hz[q] = __hfma2(w1, hs, hz[q]);
                        hn[q] = __hfma2(w2, hs, hn[q]);
                    }
                }
            }
        }

        #pragma unroll
        for (int q = 0; q < 4; ++q) {
            float2 fgr = __half22float2(gr[q]), fhr = __half22float2(hr[q]);
            float2 fgz = __half22float2(gz[q]), fhz = __half22float2(hz[q]);
            float2 fgn = __half22float2(gn[q]), fhn = __half22float2(hn[q]);
            float r0 = sigm(fgr.x * INV_SCALE + fhr.x);
            float r1 = sigm(fgr.y * INV_SCALE + fhr.y);
            float z0 = sigm(fgz.x * INV_SCALE + fhz.x);
            float z1 = sigm(fgz.y * INV_SCALE + fhz.y);
            float n0 = tanh_fast(fgn.x * INV_SCALE + r0 * fhn.x);
            float n1 = tanh_fast(fgn.y * INV_SCALE + r1 * fhn.y);
            h0[q] = (1.0f - z0) * n0 + z0 * h0[q];
            h1[q] = (1.0f - z1) * n1 + z1 * h1[q];

            hw[q * 64 + lane]      = __half2half2(__float2half_rn(h0[q]));
            hw[q * 64 + 32 + lane] = __half2half2(__float2half_rn(h1[q]));

            float part = h0[q] * wfc_sh[lane] + h1[q] * wfc_sh[lane + 32];
            #pragma unroll
            for (int m = 16; m >= 1; m >>= 1)
                part += __shfl_xor_sync(0xffffffffu, part, m);
            anc[q] += __fdiv_rn(part * 2.0f, 10.0f);
            if (lane == 0) anc_sh[(pbase + q) * NP + p] = anc[q];
        }
        __syncwarp();
    }

    #pragma unroll
    for (int q = 0; q < 4; ++q) {
        float t = xyzt[(size_t)(gpt + q) * 4 + 3];
        float lg[NP];
        float mx = -1e30f;
        #pragma unroll
        for (int p = 0; p < NP; ++p) {
            float a = anc_sh[(pbase + q) * NP + p];
            float L = -__fdiv_rn(fabsf(t - a), 100.0f);
            lg[p] = L;
            mx = fmaxf(mx, L);
        }
        float s = 0.0f, o = 0.0f;
        #pragma unroll
        for (int p = 0; p < NP; ++p) {
            float w = __expf(lg[p] - mx);
            s += w;
            o += w * __half2float(embh[(pbase + q) * 320 + p * 32 + lane]);
        }
        out[(size_t)(gpt + q) * 32 + lane] = __fdiv_rn(o, s) * INV_SCALE;
    }
}

extern "C" void kernel_launch(void* const* d_in, const int* in_sizes, int n_in,
                              void* d_out, int out_size)
{
    const float*  xyzt = (const float*)d_in[0];
    const float2* tab  = (const float2*)d_in[1];
    const float*  w_ih = (const float*)d_in[2];
    const float*  w_hh = (const float*)d_in[3];
    const float*  w_fc = (const float*)d_in[4];
    float* out = (float*)d_out;

    ResParams rp;
    double B = exp((log(4096.0) - log(128.0)) / 15.0);
    for (int l = 0; l < NL; ++l) {
        double v = floor(128.0 * pow(B, (double)l));
        rp.gs[l] = 2.0f / (float)v;
    }

    cudaFuncSetAttribute(gru_kernel, cudaFuncAttributeMaxDynamicSharedMemorySize, SMEM_BYTES);

    dim3 gridT((unsigned)(((size_t)NL * TSZ) / 256));
    transpose_kernel<<<gridT, 256>>>(tab);

    dim3 gridA(NPTS / 256, NL);
    gather_kernel<<<gridA, 256>>>(xyzt, rp);

    dim3 gridB(NPTS / PTS_PER_BLOCK);
    gru_kernel<<<gridB, THREADS, SMEM_BYTES>>>(xyzt, w_ih, w_hh, w_fc, out);
}

// round 11
// speedup vs baseline: 6.7701x; 2.1358x over previous
#include <cuda_runtime.h>
#include <cuda_fp16.h>
#include <stdint.h>
#include <math.h>

#define NPTS 262144
#define NP 10
#define NL 16
#define TSZ (1u << 19)

#define SCALE 8192.0f
#define INV_SCALE (1.0f / 8192.0f)

__device__ __half g_emb[(size_t)NPTS * 320];
__device__ uint4  g_tabT[(size_t)NL * TSZ * 4];

struct ResParams { float gs[NL]; };

__device__ __forceinline__ float tanh_fast(float x) {
    float r; asm("tanh.approx.f32 %0, %1;" : "=f"(r) : "f"(x)); return r;
}
__device__ __forceinline__ float sigm_t(float x) {     // sigmoid via tanh (1 MUFU)
    return fmaf(0.5f, tanh_fast(0.5f * x), 0.5f);
}

// ===================== Kernel T: table transpose =====================
__global__ __launch_bounds__(256)
void transpose_kernel(const float2* __restrict__ tab)
{
    size_t idx = (size_t)blockIdx.x * 256 + threadIdx.x;
    unsigned u[NP];
    #pragma unroll
    for (int p = 0; p < NP; ++p) {
        float2 v = __ldg(tab + (size_t)p * ((size_t)NL * TSZ) + idx);
        __half2 h = __floats2half2_rn(v.x * SCALE, v.y * SCALE);
        u[p] = *reinterpret_cast<unsigned*>(&h);
    }
    uint4* dst = g_tabT + idx * 4;
    dst[0] = make_uint4(u[0], u[1], u[2], u[3]);
    dst[1] = make_uint4(u[4], u[5], u[6], u[7]);
    *reinterpret_cast<uint2*>(dst + 2) = make_uint2(u[8], u[9]);
}

// ===================== Kernel A: hash-grid gather =====================
__global__ __launch_bounds__(256)
void gather_kernel(const float* __restrict__ xyzt, ResParams rp)
{
    const int l    = blockIdx.y;
    const int ptid = blockIdx.x * 256 + threadIdx.x;

    const float gsv = rp.gs[l];
    float4 ptq = reinterpret_cast<const float4*>(xyzt)[ptid];
    float x = fminf(fmaxf(ptq.x, -1.0f), 1.0f);
    float y = fminf(fmaxf(ptq.y, -1.0f), 1.0f);
    float z = fminf(fmaxf(ptq.z, -1.0f), 1.0f);
    float bx = floorf(__fdiv_rn(x + 1.0f, gsv));
    float by = floorf(__fdiv_rn(y + 1.0f, gsv));
    float bz = floorf(__fdiv_rn(z + 1.0f, gsv));
    float wx = __fdiv_rn(x - (bx * gsv - 1.0f), gsv);
    float wy = __fdiv_rn(y - (by * gsv - 1.0f), gsv);
    float wz = __fdiv_rn(z - (bz * gsv - 1.0f), gsv);

    unsigned ix = (unsigned)(int)bx;
    unsigned iy = (unsigned)(int)by;
    unsigned iz = (unsigned)(int)bz;
    unsigned hy0 = iy * 2654435761u, hy1 = hy0 + 2654435761u;
    unsigned hz0 = iz * 805459861u,  hz1 = hz0 + 805459861u;

    unsigned hidx[8];
    float    wc[8];
    float wx1 = 1.0f - wx, wy1 = 1.0f - wy, wz1 = 1.0f - wz;
    #pragma unroll
    for (int c = 0; c < 8; ++c) {
        unsigned hx = ix + ((c >> 2) & 1);
        unsigned hy = (c & 2) ? hy1 : hy0;
        unsigned hz = (c & 1) ? hz1 : hz0;
        hidx[c] = (hx ^ hy ^ hz) & (TSZ - 1u);
        wc[c] = (((c >> 2) & 1) ? wx : wx1) * ((c & 2) ? wy : wy1) * ((c & 1) ? wz : wz1);
    }

    const uint4* lvl = g_tabT + (size_t)l * TSZ * 4;
    float sx[NP], sy[NP];
    #pragma unroll
    for (int p = 0; p < NP; ++p) { sx[p] = 0.0f; sy[p] = 0.0f; }

    #pragma unroll
    for (int c = 0; c < 8; ++c) {
        const uint4* s = lvl + (size_t)hidx[c] * 4;
        uint4 A = __ldg(s);
        uint4 B = __ldg(s + 1);
        uint2 C = __ldg(reinterpret_cast<const uint2*>(s + 2));
        unsigned u[NP] = {A.x, A.y, A.z, A.w, B.x, B.y, B.z, B.w, C.x, C.y};
        float w = wc[c];
        #pragma unroll
        for (int p = 0; p < NP; ++p) {
            float2 f = __half22float2(*reinterpret_cast<__half2*>(&u[p]));
            sx[p] = fmaf(w, f.x, sx[p]);
            sy[p] = fmaf(w, f.y, sy[p]);
        }
    }

    __half2* eb = reinterpret_cast<__half2*>(g_emb) + (size_t)ptid * 160 + l;
    #pragma unroll
    for (int p = 0; p < NP; ++p)
        eb[p * 16] = __floats2half2_rn(sx[p], sy[p]);
}

// ===================== Kernel B: HMMA (mma.sync) GRU =====================
// Block: 128 threads = 4 warps, 16 points/warp -> 64 pts/block.
// smem: wih [192][40 halves], whh [192][72 halves] (padded, bank-conflict-free),
//       wfc [64 f32], anc [64][10 f32].
#define GB_WIH  0
#define GB_WHH  15360
#define GB_WFC  43008
#define GB_ANC  43264
#define GB_SMEM 45824

#define WIH_STR 40
#define WHH_STR 72

__device__ __forceinline__ void mma16816(float* d, const unsigned* a,
                                         unsigned b0, unsigned b1) {
    asm volatile(
        "mma.sync.aligned.m16n8k16.row.col.f32.f16.f16.f32 "
        "{%0,%1,%2,%3}, {%4,%5,%6,%7}, {%8,%9}, {%0,%1,%2,%3};"
        : "+f"(d[0]), "+f"(d[1]), "+f"(d[2]), "+f"(d[3])
        : "r"(a[0]), "r"(a[1]), "r"(a[2]), "r"(a[3]), "r"(b0), "r"(b1));
}
__device__ __forceinline__ unsigned pack_h2(float lo, float hi) {
    __half2 h = __floats2half2_rn(lo, hi);
    return *reinterpret_cast<unsigned*>(&h);
}

__global__ __launch_bounds__(128)
void gru_mma_kernel(const float* __restrict__ xyzt,
                    const float* __restrict__ w_ih,
                    const float* __restrict__ w_hh,
                    const float* __restrict__ w_fc,
                    float* __restrict__ out)
{
    extern __shared__ char smc[];
    __half* wih  = reinterpret_cast<__half*>(smc + GB_WIH);
    __half* whh  = reinterpret_cast<__half*>(smc + GB_WHH);
    float*  wfcs = reinterpret_cast<float*>(smc + GB_WFC);
    float*  ancs = reinterpret_cast<float*>(smc + GB_ANC);

    const int tid = threadIdx.x;

    for (int i = tid; i < 192 * 32; i += 128) {
        int n = i >> 5, k = i & 31;
        wih[n * WIH_STR + k] = __float2half_rn(w_ih[i]);
    }
    for (int i = tid; i < 192 * 64; i += 128) {
        int n = i >> 6, k = i & 63;
        whh[n * WHH_STR + k] = __float2half_rn(w_hh[i]);
    }
    if (tid < 64) wfcs[tid] = w_fc[tid];
    __syncthreads();

    const int lane  = tid & 31;
    const int wrp   = tid >> 5;
    const int g     = lane >> 2;      // fragment group 0..7
    const int t4    = lane & 3;       // thread-in-group
    const int pbase = wrp * 16;
    const int gpt0  = blockIdx.x * 64 + pbase;
    const int ptA   = gpt0 + g;
    const int ptB   = gpt0 + g + 8;

    // wfc values this lane needs: cols jt*8 + t4*2 (+1)
    float wfr[16];
    #pragma unroll
    for (int jt = 0; jt < 8; ++jt) {
        wfr[2 * jt]     = wfcs[jt * 8 + t4 * 2];
        wfr[2 * jt + 1] = wfcs[jt * 8 + t4 * 2 + 1];
    }

    const __half2 inv2 = __float2half2_rn(INV_SCALE);

    float hD[8][4];
    #pragma unroll
    for (int i = 0; i < 8; ++i)
        { hD[i][0]=0.f; hD[i][1]=0.f; hD[i][2]=0.f; hD[i][3]=0.f; }
    float anc0 = 0.0f, anc1 = 0.0f;

    const __half* eA = g_emb + (size_t)ptA * 320;
    const __half* eB = g_emb + (size_t)ptB * 320;

    for (int p = 0; p < NP; ++p) {
        // --- emb A fragments (descaled to fp16) ---
        unsigned ea[2][4];
        #pragma unroll
        for (int kt = 0; kt < 2; ++kt) {
            int c0 = p * 32 + kt * 16 + t4 * 2;
            __half2 v0 = __hmul2(*reinterpret_cast<const __half2*>(eA + c0),     inv2);
            __half2 v1 = __hmul2(*reinterpret_cast<const __half2*>(eB + c0),     inv2);
            __half2 v2 = __hmul2(*reinterpret_cast<const __half2*>(eA + c0 + 8), inv2);
            __half2 v3 = __hmul2(*reinterpret_cast<const __half2*>(eB + c0 + 8), inv2);
            ea[kt][0] = *reinterpret_cast<unsigned*>(&v0);
            ea[kt][1] = *reinterpret_cast<unsigned*>(&v1);
            ea[kt][2] = *reinterpret_cast<unsigned*>(&v2);
            ea[kt][3] = *reinterpret_cast<unsigned*>(&v3);
        }
        // --- h A fragments from D-layout (register-only recirculation) ---
        unsigned ha[4][4];
        if (p > 0) {
            #pragma unroll
            for (int kt = 0; kt < 4; ++kt) {
                ha[kt][0] = pack_h2(hD[2*kt][0],   hD[2*kt][1]);
                ha[kt][1] = pack_h2(hD[2*kt][2],   hD[2*kt][3]);
                ha[kt][2] = pack_h2(hD[2*kt+1][0], hD[2*kt+1][1]);
                ha[kt][3] = pack_h2(hD[2*kt+1][2], hD[2*kt+1][3]);
            }
        }

        float fcp0 = 0.0f, fcp1 = 0.0f;

        #pragma unroll
        for (int jt = 0; jt < 8; ++jt) {
            float aR[4] = {0,0,0,0}, aZ[4] = {0,0,0,0};
            float aN[4] = {0,0,0,0}, aH[4] = {0,0,0,0};
            const int nR = (jt * 8 + g) * WIH_STR;
            const int nZ = (64 + jt * 8 + g) * WIH_STR;
            const int nN = (128 + jt * 8 + g) * WIH_STR;
            const int mR = (jt * 8 + g) * WHH_STR;
            const int mZ = (64 + jt * 8 + g) * WHH_STR;
            const int mN = (128 + jt * 8 + g) * WHH_STR;

            #pragma unroll
            for (int kt = 0; kt < 2; ++kt) {
                int ko = kt * 16 + t4 * 2;
                mma16816(aR, ea[kt],
                         *reinterpret_cast<const unsigned*>(wih + nR + ko),
                         *reinterpret_cast<const unsigned*>(wih + nR + ko + 8));
                mma16816(aZ, ea[kt],
                         *reinterpret_cast<const unsigned*>(wih + nZ + ko),
                         *reinterpret_cast<const unsigned*>(wih + nZ + ko + 8));
                mma16816(aN, ea[kt],
                         *reinterpret_cast<const unsigned*>(wih + nN + ko),
                         *reinterpret_cast<const unsigned*>(wih + nN + ko + 8));
            }
            if (p > 0) {
                #pragma unroll
                for (int kt = 0; kt < 4; ++kt) {
                    int ko = kt * 16 + t4 * 2;
                    mma16816(aR, ha[kt],
                             *reinterpret_cast<const unsigned*>(whh + mR + ko),
                             *reinterpret_cast<const unsigned*>(whh + mR + ko + 8));
                    mma16816(aZ, ha[kt],
                             *reinterpret_cast<const unsigned*>(whh + mZ + ko),
                             *reinterpret_cast<const unsigned*>(whh + mZ + ko + 8));
                    mma16816(aH, ha[kt],
                             *reinterpret_cast<const unsigned*>(whh + mN + ko),
                             *reinterpret_cast<const unsigned*>(whh + mN + ko + 8));
                }
            }
            // epilogue: 4 elements (rows g: [0],[1]; rows g+8: [2],[3])
            #pragma unroll
            for (int i = 0; i < 4; ++i) {
                float r = sigm_t(aR[i]);
                float z = sigm_t(aZ[i]);
                float n = tanh_fast(fmaf(r, aH[i], aN[i]));
                float h = fmaf(z, hD[jt][i] - n, n);   // (1-z)n + z h
                hD[jt][i] = h;
                float wv = wfr[2 * jt + (i & 1)];
                if (i < 2) fcp0 = fmaf(h, wv, fcp0);
                else       fcp1 = fmaf(h, wv, fcp1);
            }
        }
        // quad reduce (lanes 4g..4g+3 share points ptA, ptB)
        fcp0 += __shfl_xor_sync(0xffffffffu, fcp0, 1);
        fcp0 += __shfl_xor_sync(0xffffffffu, fcp0, 2);
        fcp1 += __shfl_xor_sync(0xffffffffu, fcp1, 1);
        fcp1 += __shfl_xor_sync(0xffffffffu, fcp1, 2);
        anc0 += __fdiv_rn(fcp0 * 2.0f, 10.0f);
        anc1 += __fdiv_rn(fcp1 * 2.0f, 10.0f);
        if (t4 == 0) {
            ancs[(pbase + g) * NP + p]     = anc0;
            ancs[(pbase + g + 8) * NP + p] = anc1;
        }
    }
    __syncwarp();

    // ---- softmax + output (warp handles its 16 points; lane = dim) ----
    for (int q = 0; q < 16; ++q) {
        int pt = gpt0 + q;
        float t = xyzt[(size_t)pt * 4 + 3];
        float lg[NP];
        float mx = -1e30f;
        #pragma unroll
        for (int p = 0; p < NP; ++p) {
            float a = ancs[(pbase + q) * NP + p];
            float L = -__fdiv_rn(fabsf(t - a), 100.0f);
            lg[p] = L;
            mx = fmaxf(mx, L);
        }
        float s = 0.0f, o = 0.0f;
        #pragma unroll
        for (int p = 0; p < NP; ++p) {
            float w = __expf(lg[p] - mx);
            s += w;
            o += w * __half2float(g_emb[(size_t)pt * 320 + p * 32 + lane]);
        }
        out[(size_t)pt * 32 + lane] = __fdiv_rn(o, s) * INV_SCALE;
    }
}

extern "C" void kernel_launch(void* const* d_in, const int* in_sizes, int n_in,
                              void* d_out, int out_size)
{
    const float*  xyzt = (const float*)d_in[0];
    const float2* tab  = (const float2*)d_in[1];
    const float*  w_ih = (const float*)d_in[2];
    const float*  w_hh = (const float*)d_in[3];
    const float*  w_fc = (const float*)d_in[4];
    float* out = (float*)d_out;

    ResParams rp;
    double B = exp((log(4096.0) - log(128.0)) / 15.0);
    for (int l = 0; l < NL; ++l) {
        double v = floor(128.0 * pow(B, (double)l));
        rp.gs[l] = 2.0f / (float)v;
    }

    dim3 gridT((unsigned)(((size_t)NL * TSZ) / 256));
    transpose_kernel<<<gridT, 256>>>(tab);

    dim3 gridA(NPTS / 256, NL);
    gather_kernel<<<gridA, 256>>>(xyzt, rp);

    cudaFuncSetAttribute(gru_mma_kernel, cudaFuncAttributeMaxDynamicSharedMemorySize, GB_SMEM);
    gru_mma_kernel<<<NPTS / 64, 128, GB_SMEM>>>(xyzt, w_ih, w_hh, w_fc, out);
}

// round 12
// speedup vs baseline: 8.4378x; 1.2463x over previous
#include <cuda_runtime.h>
#include <cuda_fp16.h>
#include <stdint.h>
#include <math.h>

#define NPTS 262144
#define NP 10
#define NL 16
#define TSZ (1u << 19)

#define SCALE 8192.0f
#define INV_SCALE (1.0f / 8192.0f)

// emb: per point 16 level-slots of 48B (12 half2: 10 used), 768B/pt
__device__ __half g_emb[(size_t)NPTS * 384];
__device__ uint4  g_tabT[(size_t)NL * TSZ * 4];

struct ResParams { float gs[NL]; };

__device__ __forceinline__ float tanh_fast(float x) {
    float r; asm("tanh.approx.f32 %0, %1;" : "=f"(r) : "f"(x)); return r;
}
__device__ __forceinline__ float sigm_t(float x) {
    return fmaf(0.5f, tanh_fast(0.5f * x), 0.5f);
}

// ===================== Kernel T: table transpose =====================
__global__ __launch_bounds__(256)
void transpose_kernel(const float2* __restrict__ tab)
{
    size_t idx = (size_t)blockIdx.x * 256 + threadIdx.x;
    unsigned u[NP];
    #pragma unroll
    for (int p = 0; p < NP; ++p) {
        float2 v = __ldg(tab + (size_t)p * ((size_t)NL * TSZ) + idx);
        __half2 h = __floats2half2_rn(v.x * SCALE, v.y * SCALE);
        u[p] = *reinterpret_cast<unsigned*>(&h);
    }
    uint4* dst = g_tabT + idx * 4;
    dst[0] = make_uint4(u[0], u[1], u[2], u[3]);
    dst[1] = make_uint4(u[4], u[5], u[6], u[7]);
    *reinterpret_cast<uint2*>(dst + 2) = make_uint2(u[8], u[9]);
}

// ===================== Kernel A: hash-grid gather =====================
__global__ __launch_bounds__(256)
void gather_kernel(const float* __restrict__ xyzt, ResParams rp)
{
    const int l    = blockIdx.y;
    const int ptid = blockIdx.x * 256 + threadIdx.x;

    const float gsv = rp.gs[l];
    float4 ptq = reinterpret_cast<const float4*>(xyzt)[ptid];
    float x = fminf(fmaxf(ptq.x, -1.0f), 1.0f);
    float y = fminf(fmaxf(ptq.y, -1.0f), 1.0f);
    float z = fminf(fmaxf(ptq.z, -1.0f), 1.0f);
    float bx = floorf(__fdiv_rn(x + 1.0f, gsv));
    float by = floorf(__fdiv_rn(y + 1.0f, gsv));
    float bz = floorf(__fdiv_rn(z + 1.0f, gsv));
    float wx = __fdiv_rn(x - (bx * gsv - 1.0f), gsv);
    float wy = __fdiv_rn(y - (by * gsv - 1.0f), gsv);
    float wz = __fdiv_rn(z - (bz * gsv - 1.0f), gsv);

    unsigned ix = (unsigned)(int)bx;
    unsigned iy = (unsigned)(int)by;
    unsigned iz = (unsigned)(int)bz;
    unsigned hy0 = iy * 2654435761u, hy1 = hy0 + 2654435761u;
    unsigned hz0 = iz * 805459861u,  hz1 = hz0 + 805459861u;

    unsigned hidx[8];
    float    wc[8];
    float wx1 = 1.0f - wx, wy1 = 1.0f - wy, wz1 = 1.0f - wz;
    #pragma unroll
    for (int c = 0; c < 8; ++c) {
        unsigned hx = ix + ((c >> 2) & 1);
        unsigned hy = (c & 2) ? hy1 : hy0;
        unsigned hz = (c & 1) ? hz1 : hz0;
        hidx[c] = (hx ^ hy ^ hz) & (TSZ - 1u);
        wc[c] = (((c >> 2) & 1) ? wx : wx1) * ((c & 2) ? wy : wy1) * ((c & 1) ? wz : wz1);
    }

    const uint4* lvl = g_tabT + (size_t)l * TSZ * 4;
    float sx[NP], sy[NP];
    #pragma unroll
    for (int p = 0; p < NP; ++p) { sx[p] = 0.0f; sy[p] = 0.0f; }

    // two batches of 4 corners: issue all 12 loads before consuming
    #pragma unroll
    for (int b = 0; b < 2; ++b) {
        uint4 va[4], vb[4];
        uint2 vcc[4];
        #pragma unroll
        for (int c = 0; c < 4; ++c) {
            const uint4* s = lvl + (size_t)hidx[b * 4 + c] * 4;
            va[c]  = __ldg(s);
            vb[c]  = __ldg(s + 1);
            vcc[c] = __ldg(reinterpret_cast<const uint2*>(s + 2));
        }
        #pragma unroll
        for (int c = 0; c < 4; ++c) {
            float w = wc[b * 4 + c];
            unsigned u[NP] = {va[c].x, va[c].y, va[c].z, va[c].w,
                              vb[c].x, vb[c].y, vb[c].z, vb[c].w,
                              vcc[c].x, vcc[c].y};
            #pragma unroll
            for (int p = 0; p < NP; ++p) {
                float2 f = __half22float2(*reinterpret_cast<__half2*>(&u[p]));
                sx[p] = fmaf(w, f.x, sx[p]);
                sy[p] = fmaf(w, f.y, sy[p]);
            }
        }
    }

    // contiguous 40B store into the point's 48B level-slot (16B aligned)
    unsigned up[NP];
    #pragma unroll
    for (int p = 0; p < NP; ++p) {
        __half2 h = __floats2half2_rn(sx[p], sy[p]);   // pre-scaled by 8192
        up[p] = *reinterpret_cast<unsigned*>(&h);
    }
    char* dst = reinterpret_cast<char*>(g_emb) + (size_t)ptid * 768 + l * 48;
    *reinterpret_cast<uint4*>(dst)      = make_uint4(up[0], up[1], up[2], up[3]);
    *reinterpret_cast<uint4*>(dst + 16) = make_uint4(up[4], up[5], up[6], up[7]);
    *reinterpret_cast<uint2*>(dst + 32) = make_uint2(up[8], up[9]);
}

// ===================== Kernel B: HMMA GRU + output =====================
// smem: wih [192][80 halves] (LDS.64-permuted), whh [192][80], wfc, anc
#define GB_WIH  0
#define GB_WHH  30720
#define GB_WFC  61440
#define GB_ANC  61696
#define GB_SMEM 64256

#define W_STR 80   // halves per row; 40 words ≡ 8 (mod 32) -> conflict-free per half-warp

__device__ __forceinline__ void mma16816(float* d, const unsigned* a,
                                         unsigned b0, unsigned b1) {
    asm volatile(
        "mma.sync.aligned.m16n8k16.row.col.f32.f16.f16.f32 "
        "{%0,%1,%2,%3}, {%4,%5,%6,%7}, {%8,%9}, {%0,%1,%2,%3};"
        : "+f"(d[0]), "+f"(d[1]), "+f"(d[2]), "+f"(d[3])
        : "r"(a[0]), "r"(a[1]), "r"(a[2]), "r"(a[3]), "r"(b0), "r"(b1));
}
__device__ __forceinline__ unsigned pack_h2(float lo, float hi) {
    __half2 h = __floats2half2_rn(lo, hi);
    return *reinterpret_cast<unsigned*>(&h);
}
// permuted slot within a 16-half k-block: {k0,k1,k8,k9} per quad-thread
__device__ __forceinline__ int wperm(int n, int k) {
    int kt = k >> 4, r = k & 15;
    int slot = ((r & 7) >> 1) * 4 + (r >> 3) * 2 + (r & 1);
    return n * W_STR + kt * 16 + slot;
}

__global__ __launch_bounds__(128)
void gru_mma_kernel(const float* __restrict__ xyzt,
                    const float* __restrict__ w_ih,
                    const float* __restrict__ w_hh,
                    const float* __restrict__ w_fc,
                    float* __restrict__ out)
{
    extern __shared__ char smc[];
    __half* wih  = reinterpret_cast<__half*>(smc + GB_WIH);
    __half* whh  = reinterpret_cast<__half*>(smc + GB_WHH);
    float*  wfcs = reinterpret_cast<float*>(smc + GB_WFC);
    float*  ancs = reinterpret_cast<float*>(smc + GB_ANC);

    const int tid = threadIdx.x;

    for (int i = tid; i < 192 * 32; i += 128) {
        int n = i >> 5, k = i & 31;
        wih[wperm(n, k)] = __float2half_rn(w_ih[i]);
    }
    for (int i = tid; i < 192 * 64; i += 128) {
        int n = i >> 6, k = i & 63;
        whh[wperm(n, k)] = __float2half_rn(w_hh[i]);
    }
    if (tid < 64) wfcs[tid] = w_fc[tid];
    __syncthreads();

    const int lane  = tid & 31;
    const int wrp   = tid >> 5;
    const int g     = lane >> 2;
    const int t4    = lane & 3;
    const int pbase = wrp * 16;
    const int gpt0  = blockIdx.x * 64 + pbase;
    const int ptA   = gpt0 + g;
    const int ptB   = gpt0 + g + 8;

    float wfr[16];
    #pragma unroll
    for (int jt = 0; jt < 8; ++jt) {
        wfr[2 * jt]     = wfcs[jt * 8 + t4 * 2];
        wfr[2 * jt + 1] = wfcs[jt * 8 + t4 * 2 + 1];
    }

    const __half2 inv2 = __float2half2_rn(INV_SCALE);

    float hD[8][4];
    #pragma unroll
    for (int i = 0; i < 8; ++i)
        { hD[i][0]=0.f; hD[i][1]=0.f; hD[i][2]=0.f; hD[i][3]=0.f; }
    float anc0 = 0.0f, anc1 = 0.0f;

    const __half* eA = g_emb + (size_t)ptA * 384;
    const __half* eB = g_emb + (size_t)ptB * 384;

    for (int p = 0; p < NP; ++p) {
        // emb A fragments: dim pair (2l,2l+1) lives at half2 slot l*12+p
        unsigned ea[2][4];
        #pragma unroll
        for (int kt = 0; kt < 2; ++kt) {
            int l0 = kt * 8 + t4;
            __half2 v0 = __hmul2(*reinterpret_cast<const __half2*>(eA + (l0 * 12 + p) * 2), inv2);
            __half2 v1 = __hmul2(*reinterpret_cast<const __half2*>(eB + (l0 * 12 + p) * 2), inv2);
            __half2 v2 = __hmul2(*reinterpret_cast<const __half2*>(eA + ((l0 + 4) * 12 + p) * 2), inv2);
            __half2 v3 = __hmul2(*reinterpret_cast<const __half2*>(eB + ((l0 + 4) * 12 + p) * 2), inv2);
            ea[kt][0] = *reinterpret_cast<unsigned*>(&v0);
            ea[kt][1] = *reinterpret_cast<unsigned*>(&v1);
            ea[kt][2] = *reinterpret_cast<unsigned*>(&v2);
            ea[kt][3] = *reinterpret_cast<unsigned*>(&v3);
        }
        unsigned ha[4][4];
        if (p > 0) {
            #pragma unroll
            for (int kt = 0; kt < 4; ++kt) {
                ha[kt][0] = pack_h2(hD[2*kt][0],   hD[2*kt][1]);
                ha[kt][1] = pack_h2(hD[2*kt][2],   hD[2*kt][3]);
                ha[kt][2] = pack_h2(hD[2*kt+1][0], hD[2*kt+1][1]);
                ha[kt][3] = pack_h2(hD[2*kt+1][2], hD[2*kt+1][3]);
            }
        }

        float fcp0 = 0.0f, fcp1 = 0.0f;

        #pragma unroll
        for (int jt = 0; jt < 8; ++jt) {
            float aR[4] = {0,0,0,0}, aZ[4] = {0,0,0,0};
            float aN[4] = {0,0,0,0}, aH[4] = {0,0,0,0};
            const int nR = (jt * 8 + g) * W_STR;
            const int nZ = (64 + jt * 8 + g) * W_STR;
            const int nN = (128 + jt * 8 + g) * W_STR;
            const int mR = nR, mZ = nZ, mN = nN;   // same row indices in whh

            #pragma unroll
            for (int kt = 0; kt < 2; ++kt) {
                int ko = kt * 16 + t4 * 4;
                uint2 bR = *reinterpret_cast<const uint2*>(wih + nR + ko);
                uint2 bZ = *reinterpret_cast<const uint2*>(wih + nZ + ko);
                uint2 bN = *reinterpret_cast<const uint2*>(wih + nN + ko);
                mma16816(aR, ea[kt], bR.x, bR.y);
                mma16816(aZ, ea[kt], bZ.x, bZ.y);
                mma16816(aN, ea[kt], bN.x, bN.y);
            }
            if (p > 0) {
                #pragma unroll
                for (int kt = 0; kt < 4; ++kt) {
                    int ko = kt * 16 + t4 * 4;
                    uint2 bR = *reinterpret_cast<const uint2*>(whh + mR + ko);
                    uint2 bZ = *reinterpret_cast<const uint2*>(whh + mZ + ko);
                    uint2 bH = *reinterpret_cast<const uint2*>(whh + mN + ko);
                    mma16816(aR, ha[kt], bR.x, bR.y);
                    mma16816(aZ, ha[kt], bZ.x, bZ.y);
                    mma16816(aH, ha[kt], bH.x, bH.y);
                }
            }
            #pragma unroll
            for (int i = 0; i < 4; ++i) {
                float r = sigm_t(aR[i]);
                float z = sigm_t(aZ[i]);
                float n = tanh_fast(fmaf(r, aH[i], aN[i]));
                float h = fmaf(z, hD[jt][i] - n, n);
                hD[jt][i] = h;
                float wv = wfr[2 * jt + (i & 1)];
                if (i < 2) fcp0 = fmaf(h, wv, fcp0);
                else       fcp1 = fmaf(h, wv, fcp1);
            }
        }
        fcp0 += __shfl_xor_sync(0xffffffffu, fcp0, 1);
        fcp0 += __shfl_xor_sync(0xffffffffu, fcp0, 2);
        fcp1 += __shfl_xor_sync(0xffffffffu, fcp1, 1);
        fcp1 += __shfl_xor_sync(0xffffffffu, fcp1, 2);
        anc0 += __fdiv_rn(fcp0 * 2.0f, 10.0f);
        anc1 += __fdiv_rn(fcp1 * 2.0f, 10.0f);
        if (t4 == 0) {
            ancs[(pbase + g) * NP + p]     = anc0;
            ancs[(pbase + g + 8) * NP + p] = anc1;
        }
    }
    __syncwarp();

    // ---- softmax + output (warp = its 16 points; lane = dim) ----
    for (int q = 0; q < 16; ++q) {
        int pt = gpt0 + q;
        float t = xyzt[(size_t)pt * 4 + 3];
        float lg[NP];
        float mx = -1e30f;
        #pragma unroll
        for (int p = 0; p < NP; ++p) {
            float a = ancs[(pbase + q) * NP + p];
            float L = -__fdiv_rn(fabsf(t - a), 100.0f);
            lg[p] = L;
            mx = fmaxf(mx, L);
        }
        float s = 0.0f, o = 0.0f;
        #pragma unroll
        for (int p = 0; p < NP; ++p) {
            float w = __expf(lg[p] - mx);
            s += w;
            o += w * __half2float(g_emb[(size_t)pt * 384 + ((lane >> 1) * 12 + p) * 2 + (lane & 1)]);
        }
        out[(size_t)pt * 32 + lane] = __fdiv_rn(o, s) * INV_SCALE;
    }
}

extern "C" void kernel_launch(void* const* d_in, const int* in_sizes, int n_in,
                              void* d_out, int out_size)
{
    const float*  xyzt = (const float*)d_in[0];
    const float2* tab  = (const float2*)d_in[1];
    const float*  w_ih = (const float*)d_in[2];
    const float*  w_hh = (const float*)d_in[3];
    const float*  w_fc = (const float*)d_in[4];
    float* out = (float*)d_out;

    ResParams rp;
    double B = exp((log(4096.0) - log(128.0)) / 15.0);
    for (int l = 0; l < NL; ++l) {
        double v = floor(128.0 * pow(B, (double)l));
        rp.gs[l] = 2.0f / (float)v;
    }

    dim3 gridT((unsigned)(((size_t)NL * TSZ) / 256));
    transpose_kernel<<<gridT, 256>>>(tab);

    dim3 gridA(NPTS / 256, NL);
    gather_kernel<<<gridA, 256>>>(xyzt, rp);

    cudaFuncSetAttribute(gru_mma_kernel, cudaFuncAttributeMaxDynamicSharedMemorySize, GB_SMEM);
    gru_mma_kernel<<<NPTS / 64, 128, GB_SMEM>>>(xyzt, w_ih, w_hh, w_fc, out);
}